// round 2
// baseline (speedup 1.0000x reference)
#include <cuda_runtime.h>
#include <math.h>

#define EMBED 1024
#define DFF   4096
#define BATCH 4
#define SEQ   2048
#define TOK   (BATCH * SEQ)   // 8192

// ---------------- scratch (static device allocations; allowed) ----------------
__device__ float g_Q [TOK * EMBED];
__device__ float g_K [TOK * EMBED];
__device__ float g_V [TOK * EMBED];
__device__ float g_SC[BATCH * SEQ * SEQ];
__device__ float g_A [TOK * EMBED];
__device__ float g_P1[TOK * EMBED];
__device__ float g_X [TOK * EMBED];
__device__ float g_H [TOK * DFF];
__device__ float g_P2[TOK * EMBED];

// ---------------------------------------------------------------------------
// Tiled fp32 GEMM: C[M,N] = A[M,K] @ B(+epilogue)
//   TB=false: B is [K,N] row-major (NN)
//   TB=true : B is [N,K] row-major, compute A @ B^T (NT)
// Block tile 128x128, K-tile 16, 256 threads, 8x8 per-thread microtile.
// All shapes used are exact multiples of tiles -> no bounds checks.
// Batched over blockIdx.z with element strides sA/sB/sC (residual uses sC).
// ---------------------------------------------------------------------------
template<bool TB, bool BIAS, bool RELU, bool RES>
__global__ void __launch_bounds__(256) gemm_k(
    const float* __restrict__ A, const float* __restrict__ Bm,
    const float* __restrict__ bias, const float* __restrict__ Res,
    float* __restrict__ C,
    int M, int N, int K,
    size_t sA, size_t sB, size_t sC)
{
    __shared__ float As[16][128];
    __shared__ float Bs[16][128];

    const int tid = threadIdx.x;
    const int tx  = tid & 15;
    const int ty  = tid >> 4;
    const int bx  = blockIdx.x;
    const int by  = blockIdx.y;
    const int bz  = blockIdx.z;

    const float* Ab = A  + (size_t)bz * sA;
    const float* Bb = Bm + (size_t)bz * sB;
    float*       Cb = C  + (size_t)bz * sC;

    const int rowBase = by * 128;
    const int colBase = bx * 128;

    float acc[8][8];
    #pragma unroll
    for (int i = 0; i < 8; i++)
        #pragma unroll
        for (int j = 0; j < 8; j++)
            acc[i][j] = 0.0f;

    for (int k0 = 0; k0 < K; k0 += 16) {
        // ---- load A tile (transpose into As[k][m]) ----
        #pragma unroll
        for (int i = 0; i < 2; i++) {
            int ld = tid + i * 256;          // 0..511
            int r  = ld >> 2;                // 0..127
            int c  = (ld & 3) << 2;          // 0,4,8,12
            float4 v = *reinterpret_cast<const float4*>(
                &Ab[(size_t)(rowBase + r) * K + k0 + c]);
            As[c + 0][r] = v.x; As[c + 1][r] = v.y;
            As[c + 2][r] = v.z; As[c + 3][r] = v.w;
        }
        // ---- load B tile into Bs[k][n] ----
        if (TB) {
            #pragma unroll
            for (int i = 0; i < 2; i++) {
                int ld = tid + i * 256;
                int r  = ld >> 2;            // n index 0..127
                int c  = (ld & 3) << 2;      // k offset
                float4 v = *reinterpret_cast<const float4*>(
                    &Bb[(size_t)(colBase + r) * K + k0 + c]);
                Bs[c + 0][r] = v.x; Bs[c + 1][r] = v.y;
                Bs[c + 2][r] = v.z; Bs[c + 3][r] = v.w;
            }
        } else {
            #pragma unroll
            for (int i = 0; i < 2; i++) {
                int ld = tid + i * 256;
                int r  = ld >> 5;            // k 0..15
                int c  = (ld & 31) << 2;     // n 0..124
                *reinterpret_cast<float4*>(&Bs[r][c]) =
                    *reinterpret_cast<const float4*>(
                        &Bb[(size_t)(k0 + r) * N + colBase + c]);
            }
        }
        __syncthreads();

        #pragma unroll
        for (int k = 0; k < 16; k++) {
            float4 a0 = *reinterpret_cast<const float4*>(&As[k][ty * 8]);
            float4 a1 = *reinterpret_cast<const float4*>(&As[k][ty * 8 + 4]);
            float4 b0 = *reinterpret_cast<const float4*>(&Bs[k][tx * 8]);
            float4 b1 = *reinterpret_cast<const float4*>(&Bs[k][tx * 8 + 4]);
            float a[8] = {a0.x, a0.y, a0.z, a0.w, a1.x, a1.y, a1.z, a1.w};
            float b[8] = {b0.x, b0.y, b0.z, b0.w, b1.x, b1.y, b1.z, b1.w};
            #pragma unroll
            for (int i = 0; i < 8; i++)
                #pragma unroll
                for (int j = 0; j < 8; j++)
                    acc[i][j] = fmaf(a[i], b[j], acc[i][j]);
        }
        __syncthreads();
    }

    // ---- epilogue ----
    const float* Resb = RES ? (Res + (size_t)bz * sC) : nullptr;
    #pragma unroll
    for (int i = 0; i < 8; i++) {
        int row = rowBase + ty * 8 + i;
        #pragma unroll
        for (int jj = 0; jj < 2; jj++) {
            int col = colBase + tx * 8 + jj * 4;
            float4 v;
            v.x = acc[i][jj * 4 + 0];
            v.y = acc[i][jj * 4 + 1];
            v.z = acc[i][jj * 4 + 2];
            v.w = acc[i][jj * 4 + 3];
            if (BIAS) {
                float4 bb = *reinterpret_cast<const float4*>(&bias[col]);
                v.x += bb.x; v.y += bb.y; v.z += bb.z; v.w += bb.w;
            }
            if (RES) {
                float4 rr = *reinterpret_cast<const float4*>(
                    &Resb[(size_t)row * N + col]);
                v.x += rr.x; v.y += rr.y; v.z += rr.z; v.w += rr.w;
            }
            if (RELU) {
                v.x = fmaxf(v.x, 0.0f); v.y = fmaxf(v.y, 0.0f);
                v.z = fmaxf(v.z, 0.0f); v.w = fmaxf(v.w, 0.0f);
            }
            *reinterpret_cast<float4*>(&Cb[(size_t)row * N + col]) = v;
        }
    }
}

// ---------------------------------------------------------------------------
// Row softmax over rows of length SEQ (2048). One block (256 thr) per row.
// ---------------------------------------------------------------------------
__global__ void __launch_bounds__(256) softmax_k(float* __restrict__ S)
{
    const int row = blockIdx.x;
    float* p = S + (size_t)row * SEQ;
    const int t = threadIdx.x;

    __shared__ float red[256];

    float v[8];
    float m = -1e30f;
    #pragma unroll
    for (int i = 0; i < 8; i++) {
        v[i] = p[t + i * 256];
        m = fmaxf(m, v[i]);
    }
    red[t] = m;
    __syncthreads();
    #pragma unroll
    for (int s = 128; s > 0; s >>= 1) {
        if (t < s) red[t] = fmaxf(red[t], red[t + s]);
        __syncthreads();
    }
    m = red[0];
    __syncthreads();

    float sum = 0.0f;
    #pragma unroll
    for (int i = 0; i < 8; i++) {
        v[i] = expf(v[i] - m);
        sum += v[i];
    }
    red[t] = sum;
    __syncthreads();
    #pragma unroll
    for (int s = 128; s > 0; s >>= 1) {
        if (t < s) red[t] += red[t + s];
        __syncthreads();
    }
    const float inv = 1.0f / red[0];

    #pragma unroll
    for (int i = 0; i < 8; i++)
        p[t + i * 256] = v[i] * inv;
}

// ---------------------------------------------------------------------------
// LayerNorm over rows of length EMBED (1024). One block (256 thr) per row.
// out = (x - mean) * rsqrt(var + 1e-5) * g + b   (biased variance, like jnp.var)
// ---------------------------------------------------------------------------
__global__ void __launch_bounds__(256) layernorm_k(
    const float* __restrict__ in,
    const float* __restrict__ g,
    const float* __restrict__ b,
    float* __restrict__ out)
{
    const int row = blockIdx.x;
    const float* p = in + (size_t)row * EMBED;
    const int t = threadIdx.x;

    __shared__ float r1[256];
    __shared__ float r2[256];

    float4 v = *reinterpret_cast<const float4*>(&p[t * 4]);
    float s  = v.x + v.y + v.z + v.w;
    float sq = v.x * v.x + v.y * v.y + v.z * v.z + v.w * v.w;

    r1[t] = s; r2[t] = sq;
    __syncthreads();
    #pragma unroll
    for (int st = 128; st > 0; st >>= 1) {
        if (t < st) { r1[t] += r1[t + st]; r2[t] += r2[t + st]; }
        __syncthreads();
    }
    const float mean = r1[0] * (1.0f / EMBED);
    const float var  = r2[0] * (1.0f / EMBED) - mean * mean;
    const float rstd = rsqrtf(var + 1e-5f);

    float4 gg = *reinterpret_cast<const float4*>(&g[t * 4]);
    float4 bb = *reinterpret_cast<const float4*>(&b[t * 4]);
    float4 o;
    o.x = (v.x - mean) * rstd * gg.x + bb.x;
    o.y = (v.y - mean) * rstd * gg.y + bb.y;
    o.z = (v.z - mean) * rstd * gg.z + bb.z;
    o.w = (v.w - mean) * rstd * gg.w + bb.w;
    *reinterpret_cast<float4*>(&out[(size_t)row * EMBED + t * 4]) = o;
}

// ---------------------------------------------------------------------------
extern "C" void kernel_launch(void* const* d_in, const int* in_sizes, int n_in,
                              void* d_out, int out_size)
{
    const float* src = (const float*)d_in[0];
    const float* Wq  = (const float*)d_in[1];
    const float* bq  = (const float*)d_in[2];
    const float* Wk  = (const float*)d_in[3];
    const float* bk  = (const float*)d_in[4];
    const float* Wv  = (const float*)d_in[5];
    const float* bv  = (const float*)d_in[6];
    const float* Wo  = (const float*)d_in[7];
    const float* bo  = (const float*)d_in[8];
    const float* W1  = (const float*)d_in[9];
    const float* b1  = (const float*)d_in[10];
    const float* W2  = (const float*)d_in[11];
    const float* b2  = (const float*)d_in[12];
    const float* g1  = (const float*)d_in[13];
    const float* be1 = (const float*)d_in[14];
    const float* g2  = (const float*)d_in[15];
    const float* be2 = (const float*)d_in[16];

    float *Q, *Kp, *V, *SC, *A, *P1, *X, *H, *P2;
    cudaGetSymbolAddress((void**)&Q,  g_Q);
    cudaGetSymbolAddress((void**)&Kp, g_K);
    cudaGetSymbolAddress((void**)&V,  g_V);
    cudaGetSymbolAddress((void**)&SC, g_SC);
    cudaGetSymbolAddress((void**)&A,  g_A);
    cudaGetSymbolAddress((void**)&P1, g_P1);
    cudaGetSymbolAddress((void**)&X,  g_X);
    cudaGetSymbolAddress((void**)&H,  g_H);
    cudaGetSymbolAddress((void**)&P2, g_P2);

    const dim3 blk(256);
    const size_t sQ  = (size_t)SEQ * EMBED;   // per-batch stride, Q/K/V/attn
    const size_t sS  = (size_t)SEQ * SEQ;     // per-batch stride, scores

    // Q/K/V projections: [8192,1024] = src[8192,1024] @ W[1024,1024] + b
    gemm_k<false, true, false, false><<<dim3(EMBED / 128, TOK / 128, 1), blk>>>(
        src, Wq, bq, nullptr, Q, TOK, EMBED, EMBED, 0, 0, 0);
    gemm_k<false, true, false, false><<<dim3(EMBED / 128, TOK / 128, 1), blk>>>(
        src, Wk, bk, nullptr, Kp, TOK, EMBED, EMBED, 0, 0, 0);
    gemm_k<false, true, false, false><<<dim3(EMBED / 128, TOK / 128, 1), blk>>>(
        src, Wv, bv, nullptr, V, TOK, EMBED, EMBED, 0, 0, 0);

    // scores[b] = Q[b] @ K[b]^T  (NT, batched over z)
    gemm_k<true, false, false, false><<<dim3(SEQ / 128, SEQ / 128, BATCH), blk>>>(
        Q, Kp, nullptr, nullptr, SC, SEQ, SEQ, EMBED, sQ, sQ, sS);

    // softmax along rows
    softmax_k<<<BATCH * SEQ, 256>>>(SC);

    // attn[b] = P[b] @ V[b]  (NN, batched)
    gemm_k<false, false, false, false><<<dim3(EMBED / 128, SEQ / 128, BATCH), blk>>>(
        SC, V, nullptr, nullptr, A, SEQ, EMBED, SEQ, sS, sQ, sQ);

    // out-projection + bias + residual(src) -> P1
    gemm_k<false, true, false, true><<<dim3(EMBED / 128, TOK / 128, 1), blk>>>(
        A, Wo, bo, src, P1, TOK, EMBED, EMBED, 0, 0, 0);

    // LN1 -> X
    layernorm_k<<<TOK, 256>>>(P1, g1, be1, X);

    // FFN up: H = relu(X @ W1 + b1)
    gemm_k<false, true, true, false><<<dim3(DFF / 128, TOK / 128, 1), blk>>>(
        X, W1, b1, nullptr, H, TOK, DFF, EMBED, 0, 0, 0);

    // FFN down + bias + residual(X) -> P2
    gemm_k<false, true, false, true><<<dim3(EMBED / 128, TOK / 128, 1), blk>>>(
        H, W2, b2, X, P2, TOK, EMBED, DFF, 0, 0, 0);

    // LN2 -> output
    layernorm_k<<<TOK, 256>>>(P2, g2, be2, (float*)d_out);
}

// round 4
// speedup vs baseline: 2.2953x; 2.2953x over previous
#include <cuda_runtime.h>
#include <cuda_bf16.h>
#include <cstdint>
#include <math.h>

#define EMBED 1024
#define DFF   4096
#define BATCH 4
#define SEQ   2048
#define TOK   (BATCH * SEQ)   // 8192

// ---------------- scratch (static device allocations; allowed) ----------------
__device__ float g_Q [TOK * EMBED];
__device__ float g_K [TOK * EMBED];
__device__ float g_V [TOK * EMBED];
__device__ float g_SC[BATCH * SEQ * SEQ];
__device__ float g_A [TOK * EMBED];
__device__ float g_P1[TOK * EMBED];
__device__ float g_X [TOK * EMBED];
__device__ float g_H [TOK * DFF];
__device__ float g_P2[TOK * EMBED];

// ---------------- helpers ----------------
__device__ __forceinline__ uint32_t smem_u32(const void* p) {
    uint32_t a;
    asm("{ .reg .u64 t; cvta.to.shared.u64 t, %1; cvt.u32.u64 %0, t; }" : "=r"(a) : "l"(p));
    return a;
}

#define LDSM_X4(R, addr)                                                      \
    asm volatile("ldmatrix.sync.aligned.m8n8.x4.shared.b16 {%0,%1,%2,%3}, [%4];" \
                 : "=r"((R)[0]), "=r"((R)[1]), "=r"((R)[2]), "=r"((R)[3])     \
                 : "r"(addr))

#define LDSM_X4_T(R, addr)                                                    \
    asm volatile("ldmatrix.sync.aligned.m8n8.x4.trans.shared.b16 {%0,%1,%2,%3}, [%4];" \
                 : "=r"((R)[0]), "=r"((R)[1]), "=r"((R)[2]), "=r"((R)[3])     \
                 : "r"(addr))

#define MMA16816(D, A, B0, B1)                                                \
    asm volatile("mma.sync.aligned.m16n8k16.row.col.f32.bf16.bf16.f32 "       \
                 "{%0,%1,%2,%3},{%4,%5,%6,%7},{%8,%9},{%0,%1,%2,%3};"         \
                 : "+f"((D)[0]), "+f"((D)[1]), "+f"((D)[2]), "+f"((D)[3])     \
                 : "r"((A)[0]), "r"((A)[1]), "r"((A)[2]), "r"((A)[3]),        \
                   "r"(B0), "r"(B1))

__device__ __forceinline__ uint32_t pack_bf2(__nv_bfloat16 a, __nv_bfloat16 b) {
    __nv_bfloat162 t = __halves2bfloat162(a, b);
    return *reinterpret_cast<uint32_t*>(&t);
}

// split one float4 into hi / lo bf16 quads
__device__ __forceinline__ void split4(float4 v, uint2& h, uint2& l) {
    __nv_bfloat16 h0 = __float2bfloat16(v.x), h1 = __float2bfloat16(v.y);
    __nv_bfloat16 h2 = __float2bfloat16(v.z), h3 = __float2bfloat16(v.w);
    __nv_bfloat16 l0 = __float2bfloat16(v.x - __bfloat162float(h0));
    __nv_bfloat16 l1 = __float2bfloat16(v.y - __bfloat162float(h1));
    __nv_bfloat16 l2 = __float2bfloat16(v.z - __bfloat162float(h2));
    __nv_bfloat16 l3 = __float2bfloat16(v.w - __bfloat162float(h3));
    h = make_uint2(pack_bf2(h0, h1), pack_bf2(h2, h3));
    l = make_uint2(pack_bf2(l0, l1), pack_bf2(l2, l3));
}

// ---------------- tensor-core GEMM (mma.sync bf16, 3-term fp32 split) ------
// C[M,N] = A[M,K] @ B (+bias, +residual, relu), fp32 in/out.
// TB=false: B is [K,N] row-major (NN). TB=true: B is [N,K] row-major (NT).
// CTA tile 128x128, BK=32, 256 threads (2x4 warps, 64x32 per warp),
// double-buffered SMEM staging via registers.
#define PITCH_A  80     // bytes per 32-bf16 row (padded, conflict-free ldmatrix)
#define PITCH_BK 272    // bytes per 128-bf16 row (NN layout), conflict-free
#define ATILE    (128 * PITCH_A)          // 10240

template<bool TB, bool BIAS, bool RELU, bool RES>
__global__ void __launch_bounds__(256) tgemm(
    const float* __restrict__ A, const float* __restrict__ B,
    const float* __restrict__ bias, const float* __restrict__ Res,
    float* __restrict__ C,
    int M, int N, int K, size_t sA, size_t sB, size_t sC)
{
    constexpr int BTILE = TB ? (128 * PITCH_A) : (32 * PITCH_BK); // 10240 / 8704
    constexpr int BUFB  = 2 * ATILE + 2 * BTILE;

    extern __shared__ char smem[];
    const uint32_t sb = smem_u32(smem);

    const int tid  = threadIdx.x;
    const int lane = tid & 31;
    const int wid  = tid >> 5;
    const int wm   = wid >> 2;   // 0..1
    const int wn   = wid & 3;    // 0..3

    const float* Ab = A + (size_t)blockIdx.z * sA;
    const float* Bb = B + (size_t)blockIdx.z * sB;
    float*       Cb = C + (size_t)blockIdx.z * sC;
    const int rowBase = blockIdx.y * 128;
    const int colBase = blockIdx.x * 128;
    const int ldb = TB ? K : N;

    // ldmatrix lane selectors
    const int rA = lane & 15;                               // row-in-16
    const int cA = (lane >> 4) * 16;                        // byte col sel
    const int rBt = (lane & 7) | ((lane & 16) >> 1);        // NT B rows
    const int cBt = (lane & 8) * 2;

    // per-warp ldmatrix byte offsets within tiles
    const int aoff  = (wm * 64 + rA) * PITCH_A + cA;
    const int boffN = rA * PITCH_BK + wn * 64 + cA;         // NN (trans)
    const int boffT = (wn * 32 + rBt) * PITCH_A + cBt;      // NT

    float c[4][4][4];
    #pragma unroll
    for (int i = 0; i < 4; i++)
        #pragma unroll
        for (int j = 0; j < 4; j++)
            #pragma unroll
            for (int q = 0; q < 4; q++) c[i][j][q] = 0.f;

    const int T = K >> 5;   // K-tiles of 32
    float4 pa[4], pb[4];

    // ---- global load of K-tile t into registers ----
    auto gload = [&](int t) {
        const int k0 = t << 5;
        #pragma unroll
        for (int i = 0; i < 4; i++) {
            int idx = tid + i * 256;
            int r = idx >> 3, c4 = idx & 7;
            pa[i] = *reinterpret_cast<const float4*>(
                &Ab[(size_t)(rowBase + r) * K + k0 + c4 * 4]);
        }
        if (TB) {
            #pragma unroll
            for (int i = 0; i < 4; i++) {
                int idx = tid + i * 256;
                int r = idx >> 3, c4 = idx & 7;
                pb[i] = *reinterpret_cast<const float4*>(
                    &Bb[(size_t)(colBase + r) * ldb + k0 + c4 * 4]);
            }
        } else {
            #pragma unroll
            for (int i = 0; i < 4; i++) {
                int idx = tid + i * 256;
                int k = idx >> 5, c4 = idx & 31;
                pb[i] = *reinterpret_cast<const float4*>(
                    &Bb[(size_t)(k0 + k) * ldb + colBase + c4 * 4]);
            }
        }
    };

    // ---- store registers (split hi/lo) into SMEM buffer ----
    auto sstore = [&](int buf) {
        char* base = smem + buf * BUFB;
        char* ah = base;
        char* al = base + ATILE;
        char* bh = base + 2 * ATILE;
        char* bl = bh + BTILE;
        #pragma unroll
        for (int i = 0; i < 4; i++) {
            int idx = tid + i * 256;
            int r = idx >> 3, c4 = idx & 7;
            uint2 h, l;
            split4(pa[i], h, l);
            int off = r * PITCH_A + c4 * 8;
            *reinterpret_cast<uint2*>(ah + off) = h;
            *reinterpret_cast<uint2*>(al + off) = l;
        }
        if (TB) {
            #pragma unroll
            for (int i = 0; i < 4; i++) {
                int idx = tid + i * 256;
                int r = idx >> 3, c4 = idx & 7;
                uint2 h, l;
                split4(pb[i], h, l);
                int off = r * PITCH_A + c4 * 8;
                *reinterpret_cast<uint2*>(bh + off) = h;
                *reinterpret_cast<uint2*>(bl + off) = l;
            }
        } else {
            #pragma unroll
            for (int i = 0; i < 4; i++) {
                int idx = tid + i * 256;
                int k = idx >> 5, c4 = idx & 31;
                uint2 h, l;
                split4(pb[i], h, l);
                int off = k * PITCH_BK + c4 * 8;
                *reinterpret_cast<uint2*>(bh + off) = h;
                *reinterpret_cast<uint2*>(bl + off) = l;
            }
        }
    };

    // ---- compute from SMEM buffer ----
    auto compute = [&](int buf) {
        const uint32_t base = sb + buf * BUFB;
        const uint32_t sAh = base;
        const uint32_t sAl = base + ATILE;
        const uint32_t sBh = base + 2 * ATILE;
        const uint32_t sBl = sBh + BTILE;

        uint32_t ah[4][4], al[4][4], bhf[4], blf[4];
        #pragma unroll
        for (int ks = 0; ks < 2; ks++) {
            #pragma unroll
            for (int mi = 0; mi < 4; mi++) {
                LDSM_X4(ah[mi], sAh + aoff + mi * (16 * PITCH_A) + ks * 32);
                LDSM_X4(al[mi], sAl + aoff + mi * (16 * PITCH_A) + ks * 32);
            }
            #pragma unroll
            for (int ng = 0; ng < 2; ng++) {
                if (TB) {
                    LDSM_X4(bhf, sBh + boffT + ng * (16 * PITCH_A) + ks * 32);
                    LDSM_X4(blf, sBl + boffT + ng * (16 * PITCH_A) + ks * 32);
                } else {
                    LDSM_X4_T(bhf, sBh + boffN + ks * (16 * PITCH_BK) + ng * 32);
                    LDSM_X4_T(blf, sBl + boffN + ks * (16 * PITCH_BK) + ng * 32);
                }
                const int n0 = ng * 2, n1 = ng * 2 + 1;
                #pragma unroll
                for (int mi = 0; mi < 4; mi++) {      // pass 0: Ah*Bh
                    MMA16816(c[mi][n0], ah[mi], bhf[0], bhf[1]);
                    MMA16816(c[mi][n1], ah[mi], bhf[2], bhf[3]);
                }
                #pragma unroll
                for (int mi = 0; mi < 4; mi++) {      // pass 1: Al*Bh
                    MMA16816(c[mi][n0], al[mi], bhf[0], bhf[1]);
                    MMA16816(c[mi][n1], al[mi], bhf[2], bhf[3]);
                }
                #pragma unroll
                for (int mi = 0; mi < 4; mi++) {      // pass 2: Ah*Bl
                    MMA16816(c[mi][n0], ah[mi], blf[0], blf[1]);
                    MMA16816(c[mi][n1], ah[mi], blf[2], blf[3]);
                }
            }
        }
    };

    // ---- pipeline ----
    gload(0);
    sstore(0);
    __syncthreads();
    for (int t = 0; t < T; t++) {
        const int buf = t & 1;
        if (t + 1 < T) gload(t + 1);
        compute(buf);
        __syncthreads();
        if (t + 1 < T) {
            sstore(buf ^ 1);
            __syncthreads();
        }
    }

    // ---- epilogue ----
    const int rbase = rowBase + wm * 64 + (lane >> 2);
    const int cbase = colBase + wn * 32 + (lane & 3) * 2;
    const float* Resb = RES ? (Res + (size_t)blockIdx.z * sC) : nullptr;

    #pragma unroll
    for (int mi = 0; mi < 4; mi++) {
        #pragma unroll
        for (int ni = 0; ni < 4; ni++) {
            const int col = cbase + ni * 8;
            const int r0 = rbase + mi * 16;
            const int r1 = r0 + 8;
            float2 v0 = make_float2(c[mi][ni][0], c[mi][ni][1]);
            float2 v1 = make_float2(c[mi][ni][2], c[mi][ni][3]);
            if (BIAS) {
                float2 bb = *reinterpret_cast<const float2*>(&bias[col]);
                v0.x += bb.x; v0.y += bb.y; v1.x += bb.x; v1.y += bb.y;
            }
            if (RES) {
                float2 q0 = *reinterpret_cast<const float2*>(&Resb[(size_t)r0 * N + col]);
                float2 q1 = *reinterpret_cast<const float2*>(&Resb[(size_t)r1 * N + col]);
                v0.x += q0.x; v0.y += q0.y; v1.x += q1.x; v1.y += q1.y;
            }
            if (RELU) {
                v0.x = fmaxf(v0.x, 0.f); v0.y = fmaxf(v0.y, 0.f);
                v1.x = fmaxf(v1.x, 0.f); v1.y = fmaxf(v1.y, 0.f);
            }
            *reinterpret_cast<float2*>(&Cb[(size_t)r0 * N + col]) = v0;
            *reinterpret_cast<float2*>(&Cb[(size_t)r1 * N + col]) = v1;
        }
    }
}

// ---------------- softmax over rows of length SEQ ----------------
__global__ void __launch_bounds__(256) softmax_k(float* __restrict__ S)
{
    const int row = blockIdx.x;
    float* p = S + (size_t)row * SEQ;
    const int t = threadIdx.x;
    __shared__ float red[256];

    float v[8];
    float m = -1e30f;
    #pragma unroll
    for (int i = 0; i < 8; i++) { v[i] = p[t + i * 256]; m = fmaxf(m, v[i]); }
    red[t] = m; __syncthreads();
    #pragma unroll
    for (int s = 128; s > 0; s >>= 1) { if (t < s) red[t] = fmaxf(red[t], red[t + s]); __syncthreads(); }
    m = red[0]; __syncthreads();

    float sum = 0.f;
    #pragma unroll
    for (int i = 0; i < 8; i++) { v[i] = expf(v[i] - m); sum += v[i]; }
    red[t] = sum; __syncthreads();
    #pragma unroll
    for (int s = 128; s > 0; s >>= 1) { if (t < s) red[t] += red[t + s]; __syncthreads(); }
    const float inv = 1.f / red[0];
    #pragma unroll
    for (int i = 0; i < 8; i++) p[t + i * 256] = v[i] * inv;
}

// ---------------- LayerNorm over rows of length EMBED ----------------
__global__ void __launch_bounds__(256) layernorm_k(
    const float* __restrict__ in, const float* __restrict__ g,
    const float* __restrict__ b, float* __restrict__ out)
{
    const int row = blockIdx.x;
    const float* p = in + (size_t)row * EMBED;
    const int t = threadIdx.x;
    __shared__ float r1[256], r2[256];

    float4 v = *reinterpret_cast<const float4*>(&p[t * 4]);
    r1[t] = v.x + v.y + v.z + v.w;
    r2[t] = v.x * v.x + v.y * v.y + v.z * v.z + v.w * v.w;
    __syncthreads();
    #pragma unroll
    for (int st = 128; st > 0; st >>= 1) {
        if (t < st) { r1[t] += r1[t + st]; r2[t] += r2[t + st]; }
        __syncthreads();
    }
    const float mean = r1[0] * (1.f / EMBED);
    const float var  = r2[0] * (1.f / EMBED) - mean * mean;
    const float rstd = rsqrtf(var + 1e-5f);

    float4 gg = *reinterpret_cast<const float4*>(&g[t * 4]);
    float4 bb = *reinterpret_cast<const float4*>(&b[t * 4]);
    float4 o;
    o.x = (v.x - mean) * rstd * gg.x + bb.x;
    o.y = (v.y - mean) * rstd * gg.y + bb.y;
    o.z = (v.z - mean) * rstd * gg.z + bb.z;
    o.w = (v.w - mean) * rstd * gg.w + bb.w;
    *reinterpret_cast<float4*>(&out[(size_t)row * EMBED + t * 4]) = o;
}

// ---------------------------------------------------------------------------
extern "C" void kernel_launch(void* const* d_in, const int* in_sizes, int n_in,
                              void* d_out, int out_size)
{
    const float* src = (const float*)d_in[0];
    const float* Wq  = (const float*)d_in[1];
    const float* bq  = (const float*)d_in[2];
    const float* Wk  = (const float*)d_in[3];
    const float* bk  = (const float*)d_in[4];
    const float* Wv  = (const float*)d_in[5];
    const float* bv  = (const float*)d_in[6];
    const float* Wo  = (const float*)d_in[7];
    const float* bo  = (const float*)d_in[8];
    const float* W1  = (const float*)d_in[9];
    const float* b1  = (const float*)d_in[10];
    const float* W2  = (const float*)d_in[11];
    const float* b2  = (const float*)d_in[12];
    const float* g1  = (const float*)d_in[13];
    const float* be1 = (const float*)d_in[14];
    const float* g2  = (const float*)d_in[15];
    const float* be2 = (const float*)d_in[16];

    float *Q, *Kp, *V, *SC, *A, *P1, *X, *H, *P2;
    cudaGetSymbolAddress((void**)&Q,  g_Q);
    cudaGetSymbolAddress((void**)&Kp, g_K);
    cudaGetSymbolAddress((void**)&V,  g_V);
    cudaGetSymbolAddress((void**)&SC, g_SC);
    cudaGetSymbolAddress((void**)&A,  g_A);
    cudaGetSymbolAddress((void**)&P1, g_P1);
    cudaGetSymbolAddress((void**)&X,  g_X);
    cudaGetSymbolAddress((void**)&H,  g_H);
    cudaGetSymbolAddress((void**)&P2, g_P2);

    // dynamic smem sizes (double-buffered)
    const int SM_NN = 2 * (2 * ATILE + 2 * (32 * PITCH_BK));  // 75776
    const int SM_NT = 2 * (2 * ATILE + 2 * ATILE);            // 81920

    cudaFuncSetAttribute(tgemm<false, true,  false, false>, cudaFuncAttributeMaxDynamicSharedMemorySize, SM_NN);
    cudaFuncSetAttribute(tgemm<true,  false, false, false>, cudaFuncAttributeMaxDynamicSharedMemorySize, SM_NT);
    cudaFuncSetAttribute(tgemm<false, false, false, false>, cudaFuncAttributeMaxDynamicSharedMemorySize, SM_NN);
    cudaFuncSetAttribute(tgemm<false, true,  false, true >, cudaFuncAttributeMaxDynamicSharedMemorySize, SM_NN);
    cudaFuncSetAttribute(tgemm<false, true,  true,  false>, cudaFuncAttributeMaxDynamicSharedMemorySize, SM_NN);

    const dim3 blk(256);
    const size_t sQ = (size_t)SEQ * EMBED;
    const size_t sS = (size_t)SEQ * SEQ;

    // Q/K/V projections (NN + bias)
    tgemm<false, true, false, false><<<dim3(EMBED/128, TOK/128, 1), blk, SM_NN>>>(
        src, Wq, bq, nullptr, Q, TOK, EMBED, EMBED, 0, 0, 0);
    tgemm<false, true, false, false><<<dim3(EMBED/128, TOK/128, 1), blk, SM_NN>>>(
        src, Wk, bk, nullptr, Kp, TOK, EMBED, EMBED, 0, 0, 0);
    tgemm<false, true, false, false><<<dim3(EMBED/128, TOK/128, 1), blk, SM_NN>>>(
        src, Wv, bv, nullptr, V, TOK, EMBED, EMBED, 0, 0, 0);

    // scores[b] = Q[b] @ K[b]^T  (NT, batched)
    tgemm<true, false, false, false><<<dim3(SEQ/128, SEQ/128, BATCH), blk, SM_NT>>>(
        Q, Kp, nullptr, nullptr, SC, SEQ, SEQ, EMBED, sQ, sQ, sS);

    softmax_k<<<BATCH * SEQ, 256>>>(SC);

    // attn[b] = P[b] @ V[b]  (NN, batched)
    tgemm<false, false, false, false><<<dim3(EMBED/128, SEQ/128, BATCH), blk, SM_NN>>>(
        SC, V, nullptr, nullptr, A, SEQ, EMBED, SEQ, sS, sQ, sQ);

    // out-projection + bias + residual(src)
    tgemm<false, true, false, true><<<dim3(EMBED/128, TOK/128, 1), blk, SM_NN>>>(
        A, Wo, bo, src, P1, TOK, EMBED, EMBED, 0, 0, 0);

    layernorm_k<<<TOK, 256>>>(P1, g1, be1, X);

    // FFN up: relu(X @ W1 + b1)
    tgemm<false, true, true, false><<<dim3(DFF/128, TOK/128, 1), blk, SM_NN>>>(
        X, W1, b1, nullptr, H, TOK, DFF, EMBED, 0, 0, 0);

    // FFN down + bias + residual(X)
    tgemm<false, true, false, true><<<dim3(EMBED/128, TOK/128, 1), blk, SM_NN>>>(
        H, W2, b2, X, P2, TOK, EMBED, DFF, 0, 0, 0);

    layernorm_k<<<TOK, 256>>>(P2, g2, be2, (float*)d_out);
}

// round 8
// speedup vs baseline: 2.4121x; 1.0509x over previous
#include <cuda_runtime.h>
#include <cuda_bf16.h>
#include <cstdint>
#include <math.h>

#define EMBED 1024
#define DFF   4096
#define BATCH 4
#define SEQ   2048
#define TOK   (BATCH * SEQ)   // 8192
typedef __nv_bfloat16 bf16;

// ---------------- scratch (static device allocations; allowed) ----------------
// fp32
__device__ float g_SC[BATCH * SEQ * SEQ];
__device__ float g_P1[TOK * EMBED];
__device__ float g_X [TOK * EMBED];
__device__ float g_P2[TOK * EMBED];
// bf16 hi/lo pairs
__device__ bf16 g_srcH[TOK * EMBED],  g_srcL[TOK * EMBED];
__device__ bf16 g_WqH[EMBED * EMBED], g_WqL[EMBED * EMBED];
__device__ bf16 g_WkH[EMBED * EMBED], g_WkL[EMBED * EMBED];
__device__ bf16 g_WvH[EMBED * EMBED], g_WvL[EMBED * EMBED];
__device__ bf16 g_WoH[EMBED * EMBED], g_WoL[EMBED * EMBED];
__device__ bf16 g_W1H[EMBED * DFF],   g_W1L[EMBED * DFF];
__device__ bf16 g_W2H[DFF * EMBED],   g_W2L[DFF * EMBED];
__device__ bf16 g_QH [TOK * EMBED],   g_QL [TOK * EMBED];
__device__ bf16 g_KH [TOK * EMBED],   g_KL [TOK * EMBED];
__device__ bf16 g_VH [TOK * EMBED],   g_VL [TOK * EMBED];
__device__ bf16 g_PH [BATCH * SEQ * SEQ], g_PL[BATCH * SEQ * SEQ];
__device__ bf16 g_AH [TOK * EMBED],   g_AL [TOK * EMBED];
__device__ bf16 g_XH [TOK * EMBED],   g_XL [TOK * EMBED];
__device__ bf16 g_HH [TOK * DFF],     g_HL [TOK * DFF];

// ---------------- helpers ----------------
__device__ __forceinline__ uint32_t smem_u32(const void* p) {
    uint32_t a;
    asm("{ .reg .u64 t; cvta.to.shared.u64 t, %1; cvt.u32.u64 %0, t; }" : "=r"(a) : "l"(p));
    return a;
}
__device__ __forceinline__ void cp16(uint32_t dst, const void* src) {
    asm volatile("cp.async.cg.shared.global [%0], [%1], 16;" :: "r"(dst), "l"(src));
}
#define CP_COMMIT() asm volatile("cp.async.commit_group;" ::: "memory")
#define CP_WAIT2()  asm volatile("cp.async.wait_group 2;" ::: "memory")

#define LDSM_X4(R, addr)                                                      \
    asm volatile("ldmatrix.sync.aligned.m8n8.x4.shared.b16 {%0,%1,%2,%3}, [%4];" \
                 : "=r"((R)[0]), "=r"((R)[1]), "=r"((R)[2]), "=r"((R)[3])     \
                 : "r"(addr))
#define LDSM_X4_T(R, addr)                                                    \
    asm volatile("ldmatrix.sync.aligned.m8n8.x4.trans.shared.b16 {%0,%1,%2,%3}, [%4];" \
                 : "=r"((R)[0]), "=r"((R)[1]), "=r"((R)[2]), "=r"((R)[3])     \
                 : "r"(addr))
#define MMA16816(D, A, B0, B1)                                                \
    asm volatile("mma.sync.aligned.m16n8k16.row.col.f32.bf16.bf16.f32 "       \
                 "{%0,%1,%2,%3},{%4,%5,%6,%7},{%8,%9},{%0,%1,%2,%3};"         \
                 : "+f"((D)[0]), "+f"((D)[1]), "+f"((D)[2]), "+f"((D)[3])     \
                 : "r"((A)[0]), "r"((A)[1]), "r"((A)[2]), "r"((A)[3]),        \
                   "r"(B0), "r"(B1))

__device__ __forceinline__ uint32_t pack_hi_lo(float a, float b, bool lo) {
    bf16 ha = __float2bfloat16(a), hb = __float2bfloat16(b);
    if (!lo) {
        __nv_bfloat162 t = __halves2bfloat162(ha, hb);
        return *reinterpret_cast<uint32_t*>(&t);
    }
    bf16 la = __float2bfloat16(a - __bfloat162float(ha));
    bf16 lb = __float2bfloat16(b - __bfloat162float(hb));
    __nv_bfloat162 t = __halves2bfloat162(la, lb);
    return *reinterpret_cast<uint32_t*>(&t);
}

// ---------------- split: fp32 -> bf16 hi/lo ----------------
__global__ void __launch_bounds__(256) split_k(
    const float* __restrict__ in, bf16* __restrict__ h, bf16* __restrict__ l, int n4)
{
    int i = blockIdx.x * 256 + threadIdx.x;
    if (i >= n4) return;
    float4 v = reinterpret_cast<const float4*>(in)[i];
    uint2 hh, ll;
    hh.x = pack_hi_lo(v.x, v.y, false); hh.y = pack_hi_lo(v.z, v.w, false);
    ll.x = pack_hi_lo(v.x, v.y, true);  ll.y = pack_hi_lo(v.z, v.w, true);
    reinterpret_cast<uint2*>(h)[i] = hh;
    reinterpret_cast<uint2*>(l)[i] = ll;
}

// ---------------- tensor-core GEMM (cp.async 4-stage, bf16 3-term) --------
// C = A @ B (+bias, +residual, relu). Operands pre-split bf16 hi/lo.
// TB=false: B [K,N] (NN).  TB=true: B [N,K] (NT).
// F32OUT: write fp32 C. Otherwise write bf16 hi/lo pair Ch/Cl.
#define PITCH_A  80
#define PITCH_BK 272
#define ATILE    (128 * PITCH_A)          // 10240
#define STAGES   4

template<bool TB, bool BIAS, bool RELU, bool RES, bool F32OUT>
__global__ void __launch_bounds__(256) tgemm(
    const bf16* __restrict__ Ah, const bf16* __restrict__ Al,
    const bf16* __restrict__ Bh, const bf16* __restrict__ Bl,
    const float* __restrict__ bias, const float* __restrict__ Res,
    float* __restrict__ C, bf16* __restrict__ Ch, bf16* __restrict__ Cl,
    int M, int N, int K, size_t sA, size_t sB, size_t sC)
{
    constexpr int BTILE = TB ? ATILE : (32 * PITCH_BK);      // 10240 / 8704
    constexpr int STAGE = 2 * ATILE + 2 * BTILE;             // bytes per stage

    extern __shared__ char smem[];
    const uint32_t sb = smem_u32(smem);

    const int tid  = threadIdx.x;
    const int lane = tid & 31;
    const int wid  = tid >> 5;
    const int wm   = wid >> 2;
    const int wn   = wid & 3;

    const bf16* Abh = Ah + (size_t)blockIdx.z * sA;
    const bf16* Abl = Al + (size_t)blockIdx.z * sA;
    const bf16* Bbh = Bh + (size_t)blockIdx.z * sB;
    const bf16* Bbl = Bl + (size_t)blockIdx.z * sB;
    const int rowBase = blockIdx.y * 128;
    const int colBase = blockIdx.x * 128;

    // ldmatrix lane selectors (validated layout from R4)
    const int rA  = lane & 15;
    const int cA  = (lane >> 4) * 16;
    const int rBt = (lane & 7) | ((lane & 16) >> 1);
    const int cBt = (lane & 8) * 2;
    const int aoff  = (wm * 64 + rA) * PITCH_A + cA;
    const int boffN = rA * PITCH_BK + wn * 64 + cA;
    const int boffT = (wn * 32 + rBt) * PITCH_A + cBt;

    // cp.async per-thread mapping
    const int arow0 = tid >> 2,  acol = tid & 3;    // A/NT-B: 4 chunks/row
    const int brow0 = tid >> 4,  bcol = tid & 15;   // NN-B: 16 chunks/row

    float c[4][4][4];
    #pragma unroll
    for (int i = 0; i < 4; i++)
        #pragma unroll
        for (int j = 0; j < 4; j++)
            #pragma unroll
            for (int q = 0; q < 4; q++) c[i][j][q] = 0.f;

    const int T = K >> 5;

    auto issue = [&](int t) {
        const int slot = t & (STAGES - 1);
        const uint32_t base = sb + slot * STAGE;
        const int k0 = t << 5;
        #pragma unroll
        for (int i = 0; i < 2; i++) {                   // A hi/lo
            int r = arow0 + i * 64;
            size_t g = (size_t)(rowBase + r) * K + k0 + acol * 8;
            uint32_t s = base + r * PITCH_A + acol * 16;
            cp16(s, Abh + g);
            cp16(s + ATILE, Abl + g);
        }
        if (TB) {
            #pragma unroll
            for (int i = 0; i < 2; i++) {
                int r = arow0 + i * 64;
                size_t g = (size_t)(colBase + r) * K + k0 + acol * 8;
                uint32_t s = base + 2 * ATILE + r * PITCH_A + acol * 16;
                cp16(s, Bbh + g);
                cp16(s + BTILE, Bbl + g);
            }
        } else {
            #pragma unroll
            for (int i = 0; i < 2; i++) {
                int r = brow0 + i * 16;
                size_t g = (size_t)(k0 + r) * N + colBase + bcol * 8;
                uint32_t s = base + 2 * ATILE + r * PITCH_BK + bcol * 16;
                cp16(s, Bbh + g);
                cp16(s + BTILE, Bbl + g);
            }
        }
    };

    // prologue: stages 0..STAGES-2
    #pragma unroll
    for (int s = 0; s < STAGES - 1; s++) { issue(s); CP_COMMIT(); }

    for (int t = 0; t < T; t++) {
        CP_WAIT2();
        __syncthreads();
        if (t + STAGES - 1 < T) issue(t + STAGES - 1);
        CP_COMMIT();

        const uint32_t base = sb + (t & (STAGES - 1)) * STAGE;
        const uint32_t sAh = base;
        const uint32_t sAl = base + ATILE;
        const uint32_t sBh = base + 2 * ATILE;
        const uint32_t sBl = sBh + BTILE;

        uint32_t ah[4][4], al[4][4], bhf[4], blf[4];
        #pragma unroll
        for (int ks = 0; ks < 2; ks++) {
            #pragma unroll
            for (int mi = 0; mi < 4; mi++) {
                LDSM_X4(ah[mi], sAh + aoff + mi * (16 * PITCH_A) + ks * 32);
                LDSM_X4(al[mi], sAl + aoff + mi * (16 * PITCH_A) + ks * 32);
            }
            #pragma unroll
            for (int ng = 0; ng < 2; ng++) {
                if (TB) {
                    LDSM_X4(bhf, sBh + boffT + ng * (16 * PITCH_A) + ks * 32);
                    LDSM_X4(blf, sBl + boffT + ng * (16 * PITCH_A) + ks * 32);
                } else {
                    LDSM_X4_T(bhf, sBh + boffN + ks * (16 * PITCH_BK) + ng * 32);
                    LDSM_X4_T(blf, sBl + boffN + ks * (16 * PITCH_BK) + ng * 32);
                }
                const int n0 = ng * 2, n1 = ng * 2 + 1;
                #pragma unroll
                for (int mi = 0; mi < 4; mi++) {
                    MMA16816(c[mi][n0], ah[mi], bhf[0], bhf[1]);
                    MMA16816(c[mi][n1], ah[mi], bhf[2], bhf[3]);
                }
                #pragma unroll
                for (int mi = 0; mi < 4; mi++) {
                    MMA16816(c[mi][n0], al[mi], bhf[0], bhf[1]);
                    MMA16816(c[mi][n1], al[mi], bhf[2], bhf[3]);
                }
                #pragma unroll
                for (int mi = 0; mi < 4; mi++) {
                    MMA16816(c[mi][n0], ah[mi], blf[0], blf[1]);
                    MMA16816(c[mi][n1], ah[mi], blf[2], blf[3]);
                }
            }
        }
    }

    // ---- epilogue ----
    const int rbase = rowBase + wm * 64 + (lane >> 2);
    const int cbase = colBase + wn * 32 + (lane & 3) * 2;
    const float* Resb = RES ? (Res + (size_t)blockIdx.z * sC) : nullptr;
    float*       Cb   = F32OUT ? (C + (size_t)blockIdx.z * sC) : nullptr;
    bf16* Chb = F32OUT ? nullptr : (Ch + (size_t)blockIdx.z * sC);
    bf16* Clb = F32OUT ? nullptr : (Cl + (size_t)blockIdx.z * sC);

    #pragma unroll
    for (int mi = 0; mi < 4; mi++) {
        #pragma unroll
        for (int ni = 0; ni < 4; ni++) {
            const int col = cbase + ni * 8;
            const int r0 = rbase + mi * 16;
            const int r1 = r0 + 8;
            float2 v0 = make_float2(c[mi][ni][0], c[mi][ni][1]);
            float2 v1 = make_float2(c[mi][ni][2], c[mi][ni][3]);
            if (BIAS) {
                float2 bb = *reinterpret_cast<const float2*>(&bias[col]);
                v0.x += bb.x; v0.y += bb.y; v1.x += bb.x; v1.y += bb.y;
            }
            if (RES) {
                float2 q0 = *reinterpret_cast<const float2*>(&Resb[(size_t)r0 * N + col]);
                float2 q1 = *reinterpret_cast<const float2*>(&Resb[(size_t)r1 * N + col]);
                v0.x += q0.x; v0.y += q0.y; v1.x += q1.x; v1.y += q1.y;
            }
            if (RELU) {
                v0.x = fmaxf(v0.x, 0.f); v0.y = fmaxf(v0.y, 0.f);
                v1.x = fmaxf(v1.x, 0.f); v1.y = fmaxf(v1.y, 0.f);
            }
            if (F32OUT) {
                *reinterpret_cast<float2*>(&Cb[(size_t)r0 * N + col]) = v0;
                *reinterpret_cast<float2*>(&Cb[(size_t)r1 * N + col]) = v1;
            } else {
                *reinterpret_cast<uint32_t*>(&Chb[(size_t)r0 * N + col]) = pack_hi_lo(v0.x, v0.y, false);
                *reinterpret_cast<uint32_t*>(&Chb[(size_t)r1 * N + col]) = pack_hi_lo(v1.x, v1.y, false);
                *reinterpret_cast<uint32_t*>(&Clb[(size_t)r0 * N + col]) = pack_hi_lo(v0.x, v0.y, true);
                *reinterpret_cast<uint32_t*>(&Clb[(size_t)r1 * N + col]) = pack_hi_lo(v1.x, v1.y, true);
            }
        }
    }
}

// ---------------- softmax: fp32 scores -> bf16 hi/lo probabilities ----------
__global__ void __launch_bounds__(256) softmax_k(
    const float* __restrict__ S, bf16* __restrict__ Ph, bf16* __restrict__ Pl)
{
    const int row = blockIdx.x;
    const float* p = S + (size_t)row * SEQ;
    const int t = threadIdx.x;
    __shared__ float red[256];

    float v[8];
    float m = -1e30f;
    #pragma unroll
    for (int i = 0; i < 8; i++) { v[i] = p[t * 8 + i]; m = fmaxf(m, v[i]); }
    red[t] = m; __syncthreads();
    #pragma unroll
    for (int s = 128; s > 0; s >>= 1) { if (t < s) red[t] = fmaxf(red[t], red[t + s]); __syncthreads(); }
    m = red[0]; __syncthreads();

    float sum = 0.f;
    #pragma unroll
    for (int i = 0; i < 8; i++) { v[i] = expf(v[i] - m); sum += v[i]; }
    red[t] = sum; __syncthreads();
    #pragma unroll
    for (int s = 128; s > 0; s >>= 1) { if (t < s) red[t] += red[t + s]; __syncthreads(); }
    const float inv = 1.f / red[0];

    uint4 h, l;
    #pragma unroll
    for (int i = 0; i < 8; i++) v[i] *= inv;
    h.x = pack_hi_lo(v[0], v[1], false); h.y = pack_hi_lo(v[2], v[3], false);
    h.z = pack_hi_lo(v[4], v[5], false); h.w = pack_hi_lo(v[6], v[7], false);
    l.x = pack_hi_lo(v[0], v[1], true);  l.y = pack_hi_lo(v[2], v[3], true);
    l.z = pack_hi_lo(v[4], v[5], true);  l.w = pack_hi_lo(v[6], v[7], true);
    *reinterpret_cast<uint4*>(&Ph[(size_t)row * SEQ + t * 8]) = h;
    *reinterpret_cast<uint4*>(&Pl[(size_t)row * SEQ + t * 8]) = l;
}

// ---------------- LayerNorm (optionally also emit bf16 hi/lo) ----------------
template<bool BF>
__global__ void __launch_bounds__(256) layernorm_k(
    const float* __restrict__ in, const float* __restrict__ g,
    const float* __restrict__ b, float* __restrict__ out,
    bf16* __restrict__ oh, bf16* __restrict__ ol)
{
    const int row = blockIdx.x;
    const float* p = in + (size_t)row * EMBED;
    const int t = threadIdx.x;
    __shared__ float r1[256], r2[256];

    float4 v = *reinterpret_cast<const float4*>(&p[t * 4]);
    r1[t] = v.x + v.y + v.z + v.w;
    r2[t] = v.x * v.x + v.y * v.y + v.z * v.z + v.w * v.w;
    __syncthreads();
    #pragma unroll
    for (int st = 128; st > 0; st >>= 1) {
        if (t < st) { r1[t] += r1[t + st]; r2[t] += r2[t + st]; }
        __syncthreads();
    }
    const float mean = r1[0] * (1.f / EMBED);
    const float var  = r2[0] * (1.f / EMBED) - mean * mean;
    const float rstd = rsqrtf(var + 1e-5f);

    float4 gg = *reinterpret_cast<const float4*>(&g[t * 4]);
    float4 bb = *reinterpret_cast<const float4*>(&b[t * 4]);
    float4 o;
    o.x = (v.x - mean) * rstd * gg.x + bb.x;
    o.y = (v.y - mean) * rstd * gg.y + bb.y;
    o.z = (v.z - mean) * rstd * gg.z + bb.z;
    o.w = (v.w - mean) * rstd * gg.w + bb.w;
    *reinterpret_cast<float4*>(&out[(size_t)row * EMBED + t * 4]) = o;
    if (BF) {
        uint2 h, l;
        h.x = pack_hi_lo(o.x, o.y, false); h.y = pack_hi_lo(o.z, o.w, false);
        l.x = pack_hi_lo(o.x, o.y, true);  l.y = pack_hi_lo(o.z, o.w, true);
        *reinterpret_cast<uint2*>(&oh[(size_t)row * EMBED + t * 4]) = h;
        *reinterpret_cast<uint2*>(&ol[(size_t)row * EMBED + t * 4]) = l;
    }
}

// ---------------------------------------------------------------------------
extern "C" void kernel_launch(void* const* d_in, const int* in_sizes, int n_in,
                              void* d_out, int out_size)
{
    const float* src = (const float*)d_in[0];
    const float* bq  = (const float*)d_in[2];
    const float* bk  = (const float*)d_in[4];
    const float* bv  = (const float*)d_in[6];
    const float* bo  = (const float*)d_in[8];
    const float* b1  = (const float*)d_in[10];
    const float* b2  = (const float*)d_in[12];
    const float* g1  = (const float*)d_in[13];
    const float* be1 = (const float*)d_in[14];
    const float* g2  = (const float*)d_in[15];
    const float* be2 = (const float*)d_in[16];

    float *SC, *P1, *X, *P2;
    cudaGetSymbolAddress((void**)&SC, g_SC);
    cudaGetSymbolAddress((void**)&P1, g_P1);
    cudaGetSymbolAddress((void**)&X,  g_X);
    cudaGetSymbolAddress((void**)&P2, g_P2);

    bf16 *srcH,*srcL,*WqH,*WqL,*WkH,*WkL,*WvH,*WvL,*WoH,*WoL,*W1H,*W1L,*W2H,*W2L;
    bf16 *QH,*QL,*KH,*KL,*VH,*VL,*PH,*PL,*AH,*AL,*XH,*XL,*HH,*HL;
    cudaGetSymbolAddress((void**)&srcH, g_srcH); cudaGetSymbolAddress((void**)&srcL, g_srcL);
    cudaGetSymbolAddress((void**)&WqH, g_WqH); cudaGetSymbolAddress((void**)&WqL, g_WqL);
    cudaGetSymbolAddress((void**)&WkH, g_WkH); cudaGetSymbolAddress((void**)&WkL, g_WkL);
    cudaGetSymbolAddress((void**)&WvH, g_WvH); cudaGetSymbolAddress((void**)&WvL, g_WvL);
    cudaGetSymbolAddress((void**)&WoH, g_WoH); cudaGetSymbolAddress((void**)&WoL, g_WoL);
    cudaGetSymbolAddress((void**)&W1H, g_W1H); cudaGetSymbolAddress((void**)&W1L, g_W1L);
    cudaGetSymbolAddress((void**)&W2H, g_W2H); cudaGetSymbolAddress((void**)&W2L, g_W2L);
    cudaGetSymbolAddress((void**)&QH,  g_QH ); cudaGetSymbolAddress((void**)&QL,  g_QL );
    cudaGetSymbolAddress((void**)&KH,  g_KH ); cudaGetSymbolAddress((void**)&KL,  g_KL );
    cudaGetSymbolAddress((void**)&VH,  g_VH ); cudaGetSymbolAddress((void**)&VL,  g_VL );
    cudaGetSymbolAddress((void**)&PH,  g_PH ); cudaGetSymbolAddress((void**)&PL,  g_PL );
    cudaGetSymbolAddress((void**)&AH,  g_AH ); cudaGetSymbolAddress((void**)&AL,  g_AL );
    cudaGetSymbolAddress((void**)&XH,  g_XH ); cudaGetSymbolAddress((void**)&XL,  g_XL );
    cudaGetSymbolAddress((void**)&HH,  g_HH ); cudaGetSymbolAddress((void**)&HL,  g_HL );

    const int SM_NN = STAGES * (2 * ATILE + 2 * (32 * PITCH_BK));  // 151552
    const int SM_NT = STAGES * (4 * ATILE);                        // 163840
    cudaFuncSetAttribute(tgemm<false, true,  false, false, false>, cudaFuncAttributeMaxDynamicSharedMemorySize, SM_NN);
    cudaFuncSetAttribute(tgemm<true,  false, false, false, true >, cudaFuncAttributeMaxDynamicSharedMemorySize, SM_NT);
    cudaFuncSetAttribute(tgemm<false, false, false, false, false>, cudaFuncAttributeMaxDynamicSharedMemorySize, SM_NN);
    cudaFuncSetAttribute(tgemm<false, true,  false, true,  true >, cudaFuncAttributeMaxDynamicSharedMemorySize, SM_NN);
    cudaFuncSetAttribute(tgemm<false, true,  true,  false, false>, cudaFuncAttributeMaxDynamicSharedMemorySize, SM_NN);

    const dim3 blk(256);
    const size_t sQ = (size_t)SEQ * EMBED;
    const size_t sS = (size_t)SEQ * SEQ;

    // ---- one-time splits ----
    split_k<<<(TOK*EMBED/4 + 255)/256, 256>>>(src, srcH, srcL, TOK*EMBED/4);
    split_k<<<(EMBED*EMBED/4 + 255)/256, 256>>>((const float*)d_in[1], WqH, WqL, EMBED*EMBED/4);
    split_k<<<(EMBED*EMBED/4 + 255)/256, 256>>>((const float*)d_in[3], WkH, WkL, EMBED*EMBED/4);
    split_k<<<(EMBED*EMBED/4 + 255)/256, 256>>>((const float*)d_in[5], WvH, WvL, EMBED*EMBED/4);
    split_k<<<(EMBED*EMBED/4 + 255)/256, 256>>>((const float*)d_in[7], WoH, WoL, EMBED*EMBED/4);
    split_k<<<(EMBED*DFF/4 + 255)/256, 256>>>((const float*)d_in[9],  W1H, W1L, EMBED*DFF/4);
    split_k<<<(DFF*EMBED/4 + 255)/256, 256>>>((const float*)d_in[11], W2H, W2L, DFF*EMBED/4);

    // ---- Q/K/V projections (NN + bias, bf16-pair out) ----
    tgemm<false, true, false, false, false><<<dim3(EMBED/128, TOK/128, 1), blk, SM_NN>>>(
        srcH, srcL, WqH, WqL, bq, nullptr, nullptr, QH, QL, TOK, EMBED, EMBED, 0, 0, 0);
    tgemm<false, true, false, false, false><<<dim3(EMBED/128, TOK/128, 1), blk, SM_NN>>>(
        srcH, srcL, WkH, WkL, bk, nullptr, nullptr, KH, KL, TOK, EMBED, EMBED, 0, 0, 0);
    tgemm<false, true, false, false, false><<<dim3(EMBED/128, TOK/128, 1), blk, SM_NN>>>(
        srcH, srcL, WvH, WvL, bv, nullptr, nullptr, VH, VL, TOK, EMBED, EMBED, 0, 0, 0);

    // ---- scores = Q @ K^T (NT, batched, fp32 out) ----
    tgemm<true, false, false, false, true><<<dim3(SEQ/128, SEQ/128, BATCH), blk, SM_NT>>>(
        QH, QL, KH, KL, nullptr, nullptr, SC, nullptr, nullptr, SEQ, SEQ, EMBED, sQ, sQ, sS);

    softmax_k<<<BATCH * SEQ, 256>>>(SC, PH, PL);

    // ---- attn = P @ V (NN, batched, bf16-pair out) ----
    tgemm<false, false, false, false, false><<<dim3(EMBED/128, SEQ/128, BATCH), blk, SM_NN>>>(
        PH, PL, VH, VL, nullptr, nullptr, nullptr, AH, AL, SEQ, EMBED, SEQ, sS, sQ, sQ);

    // ---- out-proj + bias + residual(src) -> fp32 P1 ----
    tgemm<false, true, false, true, true><<<dim3(EMBED/128, TOK/128, 1), blk, SM_NN>>>(
        AH, AL, WoH, WoL, bo, src, P1, nullptr, nullptr, TOK, EMBED, EMBED, 0, 0, 0);

    layernorm_k<true><<<TOK, 256>>>(P1, g1, be1, X, XH, XL);

    // ---- FFN up: relu(X @ W1 + b1) -> bf16 pair ----
    tgemm<false, true, true, false, false><<<dim3(DFF/128, TOK/128, 1), blk, SM_NN>>>(
        XH, XL, W1H, W1L, b1, nullptr, nullptr, HH, HL, TOK, DFF, EMBED, 0, 0, 0);

    // ---- FFN down + bias + residual(X) -> fp32 P2 ----
    tgemm<false, true, false, true, true><<<dim3(EMBED/128, TOK/128, 1), blk, SM_NN>>>(
        HH, HL, W2H, W2L, b2, X, P2, nullptr, nullptr, TOK, EMBED, DFF, 0, 0, 0);

    layernorm_k<false><<<TOK, 256>>>(P2, g2, be2, (float*)d_out, nullptr, nullptr);
}

// round 12
// speedup vs baseline: 2.7129x; 1.1247x over previous
#include <cuda_runtime.h>
#include <cuda_bf16.h>
#include <cstdint>
#include <math.h>

#define EMBED 1024
#define DFF   4096
#define BATCH 4
#define SEQ   2048
#define TOK   (BATCH * SEQ)   // 8192
typedef __nv_bfloat16 bf16;

// ---------------- scratch (static device allocations; allowed) ----------------
__device__ float g_SC[BATCH * SEQ * SEQ];
__device__ float g_P1[TOK * EMBED];
__device__ float g_X [TOK * EMBED];
__device__ float g_P2[TOK * EMBED];
__device__ bf16 g_srcH[TOK * EMBED],  g_srcL[TOK * EMBED];
__device__ bf16 g_WqH[EMBED * EMBED], g_WqL[EMBED * EMBED];
__device__ bf16 g_WkH[EMBED * EMBED], g_WkL[EMBED * EMBED];
__device__ bf16 g_WvH[EMBED * EMBED], g_WvL[EMBED * EMBED];
__device__ bf16 g_WoH[EMBED * EMBED], g_WoL[EMBED * EMBED];
__device__ bf16 g_W1H[EMBED * DFF],   g_W1L[EMBED * DFF];
__device__ bf16 g_W2H[DFF * EMBED],   g_W2L[DFF * EMBED];
__device__ bf16 g_QH [TOK * EMBED],   g_QL [TOK * EMBED];
__device__ bf16 g_KH [TOK * EMBED],   g_KL [TOK * EMBED];
__device__ bf16 g_VH [TOK * EMBED],   g_VL [TOK * EMBED];
__device__ bf16 g_PH [BATCH * SEQ * SEQ], g_PL[BATCH * SEQ * SEQ];
__device__ bf16 g_AH [TOK * EMBED],   g_AL [TOK * EMBED];
__device__ bf16 g_XH [TOK * EMBED],   g_XL [TOK * EMBED];
__device__ bf16 g_HH [TOK * DFF],     g_HL [TOK * DFF];

// ---------------- helpers ----------------
__device__ __forceinline__ uint32_t smem_u32(const void* p) {
    uint32_t a;
    asm("{ .reg .u64 t; cvta.to.shared.u64 t, %1; cvt.u32.u64 %0, t; }" : "=r"(a) : "l"(p));
    return a;
}
__device__ __forceinline__ void cp16(uint32_t dst, const void* src) {
    asm volatile("cp.async.cg.shared.global [%0], [%1], 16;" :: "r"(dst), "l"(src));
}
#define CP_COMMIT() asm volatile("cp.async.commit_group;" ::: "memory")
#define CP_WAIT2()  asm volatile("cp.async.wait_group 2;" ::: "memory")

#define LDSM_X4(R, addr)                                                      \
    asm volatile("ldmatrix.sync.aligned.m8n8.x4.shared.b16 {%0,%1,%2,%3}, [%4];" \
                 : "=r"((R)[0]), "=r"((R)[1]), "=r"((R)[2]), "=r"((R)[3])     \
                 : "r"(addr))
#define LDSM_X4_T(R, addr)                                                    \
    asm volatile("ldmatrix.sync.aligned.m8n8.x4.trans.shared.b16 {%0,%1,%2,%3}, [%4];" \
                 : "=r"((R)[0]), "=r"((R)[1]), "=r"((R)[2]), "=r"((R)[3])     \
                 : "r"(addr))
#define MMA16816(D, A, B0, B1)                                                \
    asm volatile("mma.sync.aligned.m16n8k16.row.col.f32.bf16.bf16.f32 "       \
                 "{%0,%1,%2,%3},{%4,%5,%6,%7},{%8,%9},{%0,%1,%2,%3};"         \
                 : "+f"((D)[0]), "+f"((D)[1]), "+f"((D)[2]), "+f"((D)[3])     \
                 : "r"((A)[0]), "r"((A)[1]), "r"((A)[2]), "r"((A)[3]),        \
                   "r"(B0), "r"(B1))

__device__ __forceinline__ uint32_t pack_hi_lo(float a, float b, bool lo) {
    bf16 ha = __float2bfloat16(a), hb = __float2bfloat16(b);
    if (!lo) {
        __nv_bfloat162 t = __halves2bfloat162(ha, hb);
        return *reinterpret_cast<uint32_t*>(&t);
    }
    bf16 la = __float2bfloat16(a - __bfloat162float(ha));
    bf16 lb = __float2bfloat16(b - __bfloat162float(hb));
    __nv_bfloat162 t = __halves2bfloat162(la, lb);
    return *reinterpret_cast<uint32_t*>(&t);
}

// ---------------- split: fp32 -> bf16 hi/lo ----------------
__global__ void __launch_bounds__(256) split_k(
    const float* __restrict__ in, bf16* __restrict__ h, bf16* __restrict__ l, int n4)
{
    int i = blockIdx.x * 256 + threadIdx.x;
    if (i >= n4) return;
    float4 v = reinterpret_cast<const float4*>(in)[i];
    uint2 hh, ll;
    hh.x = pack_hi_lo(v.x, v.y, false); hh.y = pack_hi_lo(v.z, v.w, false);
    ll.x = pack_hi_lo(v.x, v.y, true);  ll.y = pack_hi_lo(v.z, v.w, true);
    reinterpret_cast<uint2*>(h)[i] = hh;
    reinterpret_cast<uint2*>(l)[i] = ll;
}

// ---------------- tensor-core GEMM (cp.async 4-stage, bf16 split) ----------
// C = A @ B (+bias/residual/relu at runtime). Operands pre-split bf16 hi/lo.
// TB=false: B [K,N] (NN).  TB=true: B [N,K] (NT).
// TERMS=3: Ah*Bh + Al*Bh + Ah*Bl.  TERMS=2: (Ah+Al)*Bh  (B-lo never loaded).
// Output: if C != nullptr -> fp32; else bf16 hi/lo pair Ch/Cl.
// Epilogue options are RUNTIME (nullable ptrs + relu flag) to keep the
// number of template instantiations (and ptxas time) small.
#define PITCH_A  80
#define PITCH_BK 272
#define ATILE    (128 * PITCH_A)          // 10240
#define STAGES   4

template<bool TB, int TERMS>
__global__ void __launch_bounds__(256) tgemm(
    const bf16* __restrict__ Ah, const bf16* __restrict__ Al,
    const bf16* __restrict__ Bh, const bf16* __restrict__ Bl,
    const float* __restrict__ bias, const float* __restrict__ Res,
    float* __restrict__ C, bf16* __restrict__ Ch, bf16* __restrict__ Cl,
    int relu, int N, int K, size_t sA, size_t sB, size_t sC)
{
    constexpr int BTILE = TB ? ATILE : (32 * PITCH_BK);      // 10240 / 8704
    constexpr int NB    = (TERMS == 3) ? 2 : 1;              // B sub-tiles per stage
    constexpr int STAGE = 2 * ATILE + NB * BTILE;

    extern __shared__ char smem[];
    const uint32_t sb = smem_u32(smem);

    const int tid  = threadIdx.x;
    const int lane = tid & 31;
    const int wid  = tid >> 5;
    const int wm   = wid >> 2;
    const int wn   = wid & 3;

    const bf16* Abh = Ah + (size_t)blockIdx.z * sA;
    const bf16* Abl = Al + (size_t)blockIdx.z * sA;
    const bf16* Bbh = Bh + (size_t)blockIdx.z * sB;
    const bf16* Bbl = Bl + (size_t)blockIdx.z * sB;
    const int rowBase = blockIdx.y * 128;
    const int colBase = blockIdx.x * 128;

    // ldmatrix lane selectors (validated layout)
    const int rA  = lane & 15;
    const int cA  = (lane >> 4) * 16;
    const int rBt = (lane & 7) | ((lane & 16) >> 1);
    const int cBt = (lane & 8) * 2;
    const int aoff  = (wm * 64 + rA) * PITCH_A + cA;
    const int boffN = rA * PITCH_BK + wn * 64 + cA;
    const int boffT = (wn * 32 + rBt) * PITCH_A + cBt;

    // cp.async per-thread mapping
    const int arow0 = tid >> 2,  acol = tid & 3;
    const int brow0 = tid >> 4,  bcol = tid & 15;

    float c[4][4][4];
    #pragma unroll
    for (int i = 0; i < 4; i++)
        #pragma unroll
        for (int j = 0; j < 4; j++)
            #pragma unroll
            for (int q = 0; q < 4; q++) c[i][j][q] = 0.f;

    const int T = K >> 5;

    auto issue = [&](int t) {
        const int slot = t & (STAGES - 1);
        const uint32_t base = sb + slot * STAGE;
        const int k0 = t << 5;
        #pragma unroll
        for (int i = 0; i < 2; i++) {                   // A hi/lo
            int r = arow0 + i * 64;
            size_t g = (size_t)(rowBase + r) * K + k0 + acol * 8;
            uint32_t s = base + r * PITCH_A + acol * 16;
            cp16(s, Abh + g);
            cp16(s + ATILE, Abl + g);
        }
        if (TB) {
            #pragma unroll
            for (int i = 0; i < 2; i++) {
                int r = arow0 + i * 64;
                size_t g = (size_t)(colBase + r) * K + k0 + acol * 8;
                uint32_t s = base + 2 * ATILE + r * PITCH_A + acol * 16;
                cp16(s, Bbh + g);
                if (TERMS == 3) cp16(s + BTILE, Bbl + g);
            }
        } else {
            #pragma unroll
            for (int i = 0; i < 2; i++) {
                int r = brow0 + i * 16;
                size_t g = (size_t)(k0 + r) * N + colBase + bcol * 8;
                uint32_t s = base + 2 * ATILE + r * PITCH_BK + bcol * 16;
                cp16(s, Bbh + g);
                if (TERMS == 3) cp16(s + BTILE, Bbl + g);
            }
        }
    };

    #pragma unroll
    for (int s = 0; s < STAGES - 1; s++) { issue(s); CP_COMMIT(); }

    for (int t = 0; t < T; t++) {
        CP_WAIT2();
        __syncthreads();
        if (t + STAGES - 1 < T) issue(t + STAGES - 1);
        CP_COMMIT();

        const uint32_t base = sb + (t & (STAGES - 1)) * STAGE;
        const uint32_t sAh = base;
        const uint32_t sAl = base + ATILE;
        const uint32_t sBh = base + 2 * ATILE;
        const uint32_t sBl = sBh + BTILE;

        uint32_t ah[4][4], al[4][4], bhf[4], blf[4];
        #pragma unroll
        for (int ks = 0; ks < 2; ks++) {
            #pragma unroll
            for (int mi = 0; mi < 4; mi++) {
                LDSM_X4(ah[mi], sAh + aoff + mi * (16 * PITCH_A) + ks * 32);
                LDSM_X4(al[mi], sAl + aoff + mi * (16 * PITCH_A) + ks * 32);
            }
            #pragma unroll
            for (int ng = 0; ng < 2; ng++) {
                if (TB) {
                    LDSM_X4(bhf, sBh + boffT + ng * (16 * PITCH_A) + ks * 32);
                    if (TERMS == 3) LDSM_X4(blf, sBl + boffT + ng * (16 * PITCH_A) + ks * 32);
                } else {
                    LDSM_X4_T(bhf, sBh + boffN + ks * (16 * PITCH_BK) + ng * 32);
                    if (TERMS == 3) LDSM_X4_T(blf, sBl + boffN + ks * (16 * PITCH_BK) + ng * 32);
                }
                const int n0 = ng * 2, n1 = ng * 2 + 1;
                #pragma unroll
                for (int mi = 0; mi < 4; mi++) {
                    MMA16816(c[mi][n0], ah[mi], bhf[0], bhf[1]);
                    MMA16816(c[mi][n1], ah[mi], bhf[2], bhf[3]);
                }
                #pragma unroll
                for (int mi = 0; mi < 4; mi++) {
                    MMA16816(c[mi][n0], al[mi], bhf[0], bhf[1]);
                    MMA16816(c[mi][n1], al[mi], bhf[2], bhf[3]);
                }
                if (TERMS == 3) {
                    #pragma unroll
                    for (int mi = 0; mi < 4; mi++) {
                        MMA16816(c[mi][n0], ah[mi], blf[0], blf[1]);
                        MMA16816(c[mi][n1], ah[mi], blf[2], blf[3]);
                    }
                }
            }
        }
    }

    // ---- epilogue (runtime options; uniform branches) ----
    const int rbase = rowBase + wm * 64 + (lane >> 2);
    const int cbase = colBase + wn * 32 + (lane & 3) * 2;
    const float* Resb = Res ? (Res + (size_t)blockIdx.z * sC) : nullptr;
    float* Cb  = C  ? (C  + (size_t)blockIdx.z * sC) : nullptr;
    bf16*  Chb = Ch ? (Ch + (size_t)blockIdx.z * sC) : nullptr;
    bf16*  Clb = Cl ? (Cl + (size_t)blockIdx.z * sC) : nullptr;

    #pragma unroll
    for (int mi = 0; mi < 4; mi++) {
        #pragma unroll
        for (int ni = 0; ni < 4; ni++) {
            const int col = cbase + ni * 8;
            const int r0 = rbase + mi * 16;
            const int r1 = r0 + 8;
            float2 v0 = make_float2(c[mi][ni][0], c[mi][ni][1]);
            float2 v1 = make_float2(c[mi][ni][2], c[mi][ni][3]);
            if (bias) {
                float2 bb = *reinterpret_cast<const float2*>(&bias[col]);
                v0.x += bb.x; v0.y += bb.y; v1.x += bb.x; v1.y += bb.y;
            }
            if (Resb) {
                float2 q0 = *reinterpret_cast<const float2*>(&Resb[(size_t)r0 * N + col]);
                float2 q1 = *reinterpret_cast<const float2*>(&Resb[(size_t)r1 * N + col]);
                v0.x += q0.x; v0.y += q0.y; v1.x += q1.x; v1.y += q1.y;
            }
            if (relu) {
                v0.x = fmaxf(v0.x, 0.f); v0.y = fmaxf(v0.y, 0.f);
                v1.x = fmaxf(v1.x, 0.f); v1.y = fmaxf(v1.y, 0.f);
            }
            if (Cb) {
                *reinterpret_cast<float2*>(&Cb[(size_t)r0 * N + col]) = v0;
                *reinterpret_cast<float2*>(&Cb[(size_t)r1 * N + col]) = v1;
            } else {
                *reinterpret_cast<uint32_t*>(&Chb[(size_t)r0 * N + col]) = pack_hi_lo(v0.x, v0.y, false);
                *reinterpret_cast<uint32_t*>(&Chb[(size_t)r1 * N + col]) = pack_hi_lo(v1.x, v1.y, false);
                *reinterpret_cast<uint32_t*>(&Clb[(size_t)r0 * N + col]) = pack_hi_lo(v0.x, v0.y, true);
                *reinterpret_cast<uint32_t*>(&Clb[(size_t)r1 * N + col]) = pack_hi_lo(v1.x, v1.y, true);
            }
        }
    }
}

// ---------------- softmax: fp32 scores -> bf16 hi/lo probabilities ----------
__global__ void __launch_bounds__(256) softmax_k(
    const float* __restrict__ S, bf16* __restrict__ Ph, bf16* __restrict__ Pl)
{
    const int row = blockIdx.x;
    const float* p = S + (size_t)row * SEQ;
    const int t = threadIdx.x;
    __shared__ float red[256];

    float v[8];
    float m = -1e30f;
    #pragma unroll
    for (int i = 0; i < 8; i++) { v[i] = p[t * 8 + i]; m = fmaxf(m, v[i]); }
    red[t] = m; __syncthreads();
    #pragma unroll
    for (int s = 128; s > 0; s >>= 1) { if (t < s) red[t] = fmaxf(red[t], red[t + s]); __syncthreads(); }
    m = red[0]; __syncthreads();

    float sum = 0.f;
    #pragma unroll
    for (int i = 0; i < 8; i++) { v[i] = expf(v[i] - m); sum += v[i]; }
    red[t] = sum; __syncthreads();
    #pragma unroll
    for (int s = 128; s > 0; s >>= 1) { if (t < s) red[t] += red[t + s]; __syncthreads(); }
    const float inv = 1.f / red[0];

    uint4 h, l;
    #pragma unroll
    for (int i = 0; i < 8; i++) v[i] *= inv;
    h.x = pack_hi_lo(v[0], v[1], false); h.y = pack_hi_lo(v[2], v[3], false);
    h.z = pack_hi_lo(v[4], v[5], false); h.w = pack_hi_lo(v[6], v[7], false);
    l.x = pack_hi_lo(v[0], v[1], true);  l.y = pack_hi_lo(v[2], v[3], true);
    l.z = pack_hi_lo(v[4], v[5], true);  l.w = pack_hi_lo(v[6], v[7], true);
    *reinterpret_cast<uint4*>(&Ph[(size_t)row * SEQ + t * 8]) = h;
    *reinterpret_cast<uint4*>(&Pl[(size_t)row * SEQ + t * 8]) = l;
}

// ---------------- LayerNorm (optionally also emit bf16 hi/lo) ----------------
__global__ void __launch_bounds__(256) layernorm_k(
    const float* __restrict__ in, const float* __restrict__ g,
    const float* __restrict__ b, float* __restrict__ out,
    bf16* __restrict__ oh, bf16* __restrict__ ol)
{
    const int row = blockIdx.x;
    const float* p = in + (size_t)row * EMBED;
    const int t = threadIdx.x;
    __shared__ float r1[256], r2[256];

    float4 v = *reinterpret_cast<const float4*>(&p[t * 4]);
    r1[t] = v.x + v.y + v.z + v.w;
    r2[t] = v.x * v.x + v.y * v.y + v.z * v.z + v.w * v.w;
    __syncthreads();
    #pragma unroll
    for (int st = 128; st > 0; st >>= 1) {
        if (t < st) { r1[t] += r1[t + st]; r2[t] += r2[t + st]; }
        __syncthreads();
    }
    const float mean = r1[0] * (1.f / EMBED);
    const float var  = r2[0] * (1.f / EMBED) - mean * mean;
    const float rstd = rsqrtf(var + 1e-5f);

    float4 gg = *reinterpret_cast<const float4*>(&g[t * 4]);
    float4 bb = *reinterpret_cast<const float4*>(&b[t * 4]);
    float4 o;
    o.x = (v.x - mean) * rstd * gg.x + bb.x;
    o.y = (v.y - mean) * rstd * gg.y + bb.y;
    o.z = (v.z - mean) * rstd * gg.z + bb.z;
    o.w = (v.w - mean) * rstd * gg.w + bb.w;
    *reinterpret_cast<float4*>(&out[(size_t)row * EMBED + t * 4]) = o;
    if (oh) {
        uint2 h, l;
        h.x = pack_hi_lo(o.x, o.y, false); h.y = pack_hi_lo(o.z, o.w, false);
        l.x = pack_hi_lo(o.x, o.y, true);  l.y = pack_hi_lo(o.z, o.w, true);
        *reinterpret_cast<uint2*>(&oh[(size_t)row * EMBED + t * 4]) = h;
        *reinterpret_cast<uint2*>(&ol[(size_t)row * EMBED + t * 4]) = l;
    }
}

// ---------------------------------------------------------------------------
extern "C" void kernel_launch(void* const* d_in, const int* in_sizes, int n_in,
                              void* d_out, int out_size)
{
    const float* src = (const float*)d_in[0];
    const float* bq  = (const float*)d_in[2];
    const float* bk  = (const float*)d_in[4];
    const float* bv  = (const float*)d_in[6];
    const float* bo  = (const float*)d_in[8];
    const float* b1  = (const float*)d_in[10];
    const float* b2  = (const float*)d_in[12];
    const float* g1  = (const float*)d_in[13];
    const float* be1 = (const float*)d_in[14];
    const float* g2  = (const float*)d_in[15];
    const float* be2 = (const float*)d_in[16];

    float *SC, *P1, *X, *P2;
    cudaGetSymbolAddress((void**)&SC, g_SC);
    cudaGetSymbolAddress((void**)&P1, g_P1);
    cudaGetSymbolAddress((void**)&X,  g_X);
    cudaGetSymbolAddress((void**)&P2, g_P2);

    bf16 *srcH,*srcL,*WqH,*WqL,*WkH,*WkL,*WvH,*WvL,*WoH,*WoL,*W1H,*W1L,*W2H,*W2L;
    bf16 *QH,*QL,*KH,*KL,*VH,*VL,*PH,*PL,*AH,*AL,*XH,*XL,*HH,*HL;
    cudaGetSymbolAddress((void**)&srcH, g_srcH); cudaGetSymbolAddress((void**)&srcL, g_srcL);
    cudaGetSymbolAddress((void**)&WqH, g_WqH); cudaGetSymbolAddress((void**)&WqL, g_WqL);
    cudaGetSymbolAddress((void**)&WkH, g_WkH); cudaGetSymbolAddress((void**)&WkL, g_WkL);
    cudaGetSymbolAddress((void**)&WvH, g_WvH); cudaGetSymbolAddress((void**)&WvL, g_WvL);
    cudaGetSymbolAddress((void**)&WoH, g_WoH); cudaGetSymbolAddress((void**)&WoL, g_WoL);
    cudaGetSymbolAddress((void**)&W1H, g_W1H); cudaGetSymbolAddress((void**)&W1L, g_W1L);
    cudaGetSymbolAddress((void**)&W2H, g_W2H); cudaGetSymbolAddress((void**)&W2L, g_W2L);
    cudaGetSymbolAddress((void**)&QH,  g_QH ); cudaGetSymbolAddress((void**)&QL,  g_QL );
    cudaGetSymbolAddress((void**)&KH,  g_KH ); cudaGetSymbolAddress((void**)&KL,  g_KL );
    cudaGetSymbolAddress((void**)&VH,  g_VH ); cudaGetSymbolAddress((void**)&VL,  g_VL );
    cudaGetSymbolAddress((void**)&PH,  g_PH ); cudaGetSymbolAddress((void**)&PL,  g_PL );
    cudaGetSymbolAddress((void**)&AH,  g_AH ); cudaGetSymbolAddress((void**)&AL,  g_AL );
    cudaGetSymbolAddress((void**)&XH,  g_XH ); cudaGetSymbolAddress((void**)&XL,  g_XL );
    cudaGetSymbolAddress((void**)&HH,  g_HH ); cudaGetSymbolAddress((void**)&HL,  g_HL );

    const int SM_NN3 = STAGES * (2 * ATILE + 2 * (32 * PITCH_BK));  // 151552
    const int SM_NT3 = STAGES * (4 * ATILE);                        // 163840
    const int SM_NN2 = STAGES * (2 * ATILE + 1 * (32 * PITCH_BK));  // 116736
    cudaFuncSetAttribute(tgemm<false, 3>, cudaFuncAttributeMaxDynamicSharedMemorySize, SM_NN3);
    cudaFuncSetAttribute(tgemm<true,  3>, cudaFuncAttributeMaxDynamicSharedMemorySize, SM_NT3);
    cudaFuncSetAttribute(tgemm<false, 2>, cudaFuncAttributeMaxDynamicSharedMemorySize, SM_NN2);

    const dim3 blk(256);
    const size_t sQ = (size_t)SEQ * EMBED;
    const size_t sS = (size_t)SEQ * SEQ;

    // ---- one-time splits ----
    split_k<<<(TOK*EMBED/4 + 255)/256, 256>>>(src, srcH, srcL, TOK*EMBED/4);
    split_k<<<(EMBED*EMBED/4 + 255)/256, 256>>>((const float*)d_in[1], WqH, WqL, EMBED*EMBED/4);
    split_k<<<(EMBED*EMBED/4 + 255)/256, 256>>>((const float*)d_in[3], WkH, WkL, EMBED*EMBED/4);
    split_k<<<(EMBED*EMBED/4 + 255)/256, 256>>>((const float*)d_in[5], WvH, WvL, EMBED*EMBED/4);
    split_k<<<(EMBED*EMBED/4 + 255)/256, 256>>>((const float*)d_in[7], WoH, WoL, EMBED*EMBED/4);
    split_k<<<(EMBED*DFF/4 + 255)/256, 256>>>((const float*)d_in[9],  W1H, W1L, EMBED*DFF/4);
    split_k<<<(DFF*EMBED/4 + 255)/256, 256>>>((const float*)d_in[11], W2H, W2L, DFF*EMBED/4);

    // ---- Q/K/V projections (NN + bias, 3-term, bf16-pair out) ----
    tgemm<false, 3><<<dim3(EMBED/128, TOK/128, 1), blk, SM_NN3>>>(
        srcH, srcL, WqH, WqL, bq, nullptr, nullptr, QH, QL, 0, EMBED, EMBED, 0, 0, 0);
    tgemm<false, 3><<<dim3(EMBED/128, TOK/128, 1), blk, SM_NN3>>>(
        srcH, srcL, WkH, WkL, bk, nullptr, nullptr, KH, KL, 0, EMBED, EMBED, 0, 0, 0);
    tgemm<false, 3><<<dim3(EMBED/128, TOK/128, 1), blk, SM_NN3>>>(
        srcH, srcL, WvH, WvL, bv, nullptr, nullptr, VH, VL, 0, EMBED, EMBED, 0, 0, 0);

    // ---- scores = Q @ K^T (NT, batched, 3-term, fp32 out) ----
    tgemm<true, 3><<<dim3(SEQ/128, SEQ/128, BATCH), blk, SM_NT3>>>(
        QH, QL, KH, KL, nullptr, nullptr, SC, nullptr, nullptr, 0, SEQ, EMBED, sQ, sQ, sS);

    softmax_k<<<BATCH * SEQ, 256>>>(SC, PH, PL);

    // ---- attn = P @ V (NN, batched, 3-term, bf16-pair out) ----
    tgemm<false, 3><<<dim3(EMBED/128, SEQ/128, BATCH), blk, SM_NN3>>>(
        PH, PL, VH, VL, nullptr, nullptr, nullptr, AH, AL, 0, EMBED, SEQ, sS, sQ, sQ);

    // ---- out-proj + bias + residual(src) -> fp32 P1 (3-term) ----
    tgemm<false, 3><<<dim3(EMBED/128, TOK/128, 1), blk, SM_NN3>>>(
        AH, AL, WoH, WoL, bo, src, P1, nullptr, nullptr, 0, EMBED, EMBED, 0, 0, 0);

    layernorm_k<<<TOK, 256>>>(P1, g1, be1, X, XH, XL);

    // ---- FFN up: relu(X @ W1 + b1) -> bf16 pair (2-term) ----
    tgemm<false, 2><<<dim3(DFF/128, TOK/128, 1), blk, SM_NN2>>>(
        XH, XL, W1H, W1L, b1, nullptr, nullptr, HH, HL, 1, DFF, EMBED, 0, 0, 0);

    // ---- FFN down + bias + residual(X) -> fp32 P2 (2-term) ----
    tgemm<false, 2><<<dim3(EMBED/128, TOK/128, 1), blk, SM_NN2>>>(
        HH, HL, W2H, W2L, b2, X, P2, nullptr, nullptr, 0, EMBED, DFF, 0, 0, 0);

    layernorm_k<<<TOK, 256>>>(P2, g2, be2, (float*)d_out, nullptr, nullptr);
}

// round 13
// speedup vs baseline: 3.0407x; 1.1208x over previous
#include <cuda_runtime.h>
#include <cuda_bf16.h>
#include <cstdint>
#include <math.h>

#define EMBED 1024
#define DFF   4096
#define BATCH 4
#define SEQ   2048
#define TOK   (BATCH * SEQ)   // 8192
typedef __nv_bfloat16 bf16;

// ---------------- scratch (static device allocations; allowed) ----------------
__device__ float g_SC[BATCH * SEQ * SEQ];
__device__ float g_P1[TOK * EMBED];
__device__ float g_X [TOK * EMBED];
__device__ float g_P2[TOK * EMBED];
__device__ bf16 g_srcH[TOK * EMBED],  g_srcL[TOK * EMBED];
__device__ bf16 g_WqH[EMBED * EMBED], g_WqL[EMBED * EMBED];
__device__ bf16 g_WkH[EMBED * EMBED], g_WkL[EMBED * EMBED];
__device__ bf16 g_WvH[EMBED * EMBED], g_WvL[EMBED * EMBED];
__device__ bf16 g_WoH[EMBED * EMBED], g_WoL[EMBED * EMBED];
__device__ bf16 g_W1H[EMBED * DFF],   g_W1L[EMBED * DFF];
__device__ bf16 g_W2H[DFF * EMBED],   g_W2L[DFF * EMBED];
__device__ bf16 g_QH [TOK * EMBED],   g_QL [TOK * EMBED];
__device__ bf16 g_KH [TOK * EMBED],   g_KL [TOK * EMBED];
__device__ bf16 g_VH [TOK * EMBED],   g_VL [TOK * EMBED];
__device__ bf16 g_PH [BATCH * SEQ * SEQ], g_PL[BATCH * SEQ * SEQ];
__device__ bf16 g_AH [TOK * EMBED],   g_AL [TOK * EMBED];
__device__ bf16 g_XH [TOK * EMBED],   g_XL [TOK * EMBED];
__device__ bf16 g_HH [TOK * DFF],     g_HL [TOK * DFF];

// ---------------- helpers ----------------
__device__ __forceinline__ uint32_t smem_u32(const void* p) {
    uint32_t a;
    asm("{ .reg .u64 t; cvta.to.shared.u64 t, %1; cvt.u32.u64 %0, t; }" : "=r"(a) : "l"(p));
    return a;
}
__device__ __forceinline__ void cp16(uint32_t dst, const void* src) {
    asm volatile("cp.async.cg.shared.global [%0], [%1], 16;" :: "r"(dst), "l"(src));
}
#define CP_COMMIT() asm volatile("cp.async.commit_group;" ::: "memory")
#define CP_WAIT1()  asm volatile("cp.async.wait_group 1;" ::: "memory")

#define LDSM_X4(R, addr)                                                      \
    asm volatile("ldmatrix.sync.aligned.m8n8.x4.shared.b16 {%0,%1,%2,%3}, [%4];" \
                 : "=r"((R)[0]), "=r"((R)[1]), "=r"((R)[2]), "=r"((R)[3])     \
                 : "r"(addr))
#define LDSM_X4_T(R, addr)                                                    \
    asm volatile("ldmatrix.sync.aligned.m8n8.x4.trans.shared.b16 {%0,%1,%2,%3}, [%4];" \
                 : "=r"((R)[0]), "=r"((R)[1]), "=r"((R)[2]), "=r"((R)[3])     \
                 : "r"(addr))
#define MMA16816(D, A, B0, B1)                                                \
    asm volatile("mma.sync.aligned.m16n8k16.row.col.f32.bf16.bf16.f32 "       \
                 "{%0,%1,%2,%3},{%4,%5,%6,%7},{%8,%9},{%0,%1,%2,%3};"         \
                 : "+f"((D)[0]), "+f"((D)[1]), "+f"((D)[2]), "+f"((D)[3])     \
                 : "r"((A)[0]), "r"((A)[1]), "r"((A)[2]), "r"((A)[3]),        \
                   "r"(B0), "r"(B1))

__device__ __forceinline__ uint32_t pack_hi_lo(float a, float b, bool lo) {
    bf16 ha = __float2bfloat16(a), hb = __float2bfloat16(b);
    if (!lo) {
        __nv_bfloat162 t = __halves2bfloat162(ha, hb);
        return *reinterpret_cast<uint32_t*>(&t);
    }
    bf16 la = __float2bfloat16(a - __bfloat162float(ha));
    bf16 lb = __float2bfloat16(b - __bfloat162float(hb));
    __nv_bfloat162 t = __halves2bfloat162(la, lb);
    return *reinterpret_cast<uint32_t*>(&t);
}

// ---------------- split: fp32 -> bf16 hi/lo ----------------
__global__ void __launch_bounds__(256) split_k(
    const float* __restrict__ in, bf16* __restrict__ h, bf16* __restrict__ l, int n4)
{
    int i = blockIdx.x * 256 + threadIdx.x;
    if (i >= n4) return;
    float4 v = reinterpret_cast<const float4*>(in)[i];
    uint2 hh, ll;
    hh.x = pack_hi_lo(v.x, v.y, false); hh.y = pack_hi_lo(v.z, v.w, false);
    ll.x = pack_hi_lo(v.x, v.y, true);  ll.y = pack_hi_lo(v.z, v.w, true);
    reinterpret_cast<uint2*>(h)[i] = hh;
    reinterpret_cast<uint2*>(l)[i] = ll;
}

// ---------------- tensor-core GEMM (cp.async 3-stage, BK=64, bf16 split) ---
// C = A @ B (+bias/residual/relu at runtime). Operands pre-split bf16 hi/lo.
// TB=false: B [K,N] (NN).  TB=true: B [N,K] (NT).
// TERMS=3: Ah*Bh + Al*Bh + Ah*Bl.  TERMS=2: (Ah+Al)*Bh  (B-lo never loaded).
// Output: if C != nullptr -> fp32; else bf16 hi/lo pair Ch/Cl.
#define PITCH_A  144    // bytes per 64-bf16 row (padded; ldmatrix conflict-free)
#define PITCH_BK 272    // bytes per 128-bf16 row (NN layout)
#define ATILE    (128 * PITCH_A)          // 18432
#define STAGES   3

template<bool TB, int TERMS>
__global__ void __launch_bounds__(256) tgemm(
    const bf16* __restrict__ Ah, const bf16* __restrict__ Al,
    const bf16* __restrict__ Bh, const bf16* __restrict__ Bl,
    const float* __restrict__ bias, const float* __restrict__ Res,
    float* __restrict__ C, bf16* __restrict__ Ch, bf16* __restrict__ Cl,
    int relu, int N, int K, size_t sA, size_t sB, size_t sC)
{
    constexpr int BTILE = TB ? ATILE : (64 * PITCH_BK);      // 18432 / 17408
    constexpr int NB    = (TERMS == 3) ? 2 : 1;
    constexpr int STAGE = 2 * ATILE + NB * BTILE;

    extern __shared__ char smem[];
    const uint32_t sb = smem_u32(smem);

    const int tid  = threadIdx.x;
    const int lane = tid & 31;
    const int wid  = tid >> 5;
    const int wm   = wid >> 2;
    const int wn   = wid & 3;

    const bf16* Abh = Ah + (size_t)blockIdx.z * sA;
    const bf16* Abl = Al + (size_t)blockIdx.z * sA;
    const bf16* Bbh = Bh + (size_t)blockIdx.z * sB;
    const bf16* Bbl = Bl + (size_t)blockIdx.z * sB;
    const int rowBase = blockIdx.y * 128;
    const int colBase = blockIdx.x * 128;

    // ldmatrix lane selectors (validated layout, pitch-parameterized)
    const int rA  = lane & 15;
    const int cA  = (lane >> 4) * 16;
    const int rBt = (lane & 7) | ((lane & 16) >> 1);
    const int cBt = (lane & 8) * 2;
    const int aoff  = (wm * 64 + rA) * PITCH_A + cA;
    const int boffN = rA * PITCH_BK + wn * 64 + cA;
    const int boffT = (wn * 32 + rBt) * PITCH_A + cBt;

    float c[4][4][4];
    #pragma unroll
    for (int i = 0; i < 4; i++)
        #pragma unroll
        for (int j = 0; j < 4; j++)
            #pragma unroll
            for (int q = 0; q < 4; q++) c[i][j][q] = 0.f;

    const int T = K >> 6;   // K-tiles of 64

    auto issue = [&](int t) {
        const int slot = t % STAGES;
        const uint32_t base = sb + slot * STAGE;
        const int k0 = t << 6;
        // A tile: 128 rows x 64 cols = 1024 16B chunks
        #pragma unroll
        for (int i = 0; i < 4; i++) {
            int idx = tid + i * 256;
            int r = idx >> 3, cc = idx & 7;
            size_t g = (size_t)(rowBase + r) * K + k0 + cc * 8;
            uint32_t s = base + r * PITCH_A + cc * 16;
            cp16(s, Abh + g);
            cp16(s + ATILE, Abl + g);
        }
        if (TB) {  // B tile: 128 n-rows x 64 k-cols
            #pragma unroll
            for (int i = 0; i < 4; i++) {
                int idx = tid + i * 256;
                int r = idx >> 3, cc = idx & 7;
                size_t g = (size_t)(colBase + r) * K + k0 + cc * 8;
                uint32_t s = base + 2 * ATILE + r * PITCH_A + cc * 16;
                cp16(s, Bbh + g);
                if (TERMS == 3) cp16(s + BTILE, Bbl + g);
            }
        } else {   // B tile: 64 k-rows x 128 n-cols = 1024 16B chunks
            #pragma unroll
            for (int i = 0; i < 4; i++) {
                int idx = tid + i * 256;
                int r = idx >> 4, cc = idx & 15;
                size_t g = (size_t)(k0 + r) * N + colBase + cc * 8;
                uint32_t s = base + 2 * ATILE + r * PITCH_BK + cc * 16;
                cp16(s, Bbh + g);
                if (TERMS == 3) cp16(s + BTILE, Bbl + g);
            }
        }
    };

    #pragma unroll
    for (int s = 0; s < STAGES - 1; s++) { issue(s); CP_COMMIT(); }

    for (int t = 0; t < T; t++) {
        CP_WAIT1();
        __syncthreads();
        if (t + STAGES - 1 < T) issue(t + STAGES - 1);
        CP_COMMIT();

        const uint32_t base = sb + (t % STAGES) * STAGE;
        const uint32_t sAh = base;
        const uint32_t sAl = base + ATILE;
        const uint32_t sBh = base + 2 * ATILE;
        const uint32_t sBl = sBh + BTILE;

        uint32_t ah[4][4], al[4][4], bhf[4], blf[4];
        #pragma unroll 1
        for (int ks = 0; ks < 4; ks++) {
            #pragma unroll
            for (int mi = 0; mi < 4; mi++) {
                LDSM_X4(ah[mi], sAh + aoff + mi * (16 * PITCH_A) + ks * 32);
                LDSM_X4(al[mi], sAl + aoff + mi * (16 * PITCH_A) + ks * 32);
            }
            #pragma unroll
            for (int ng = 0; ng < 2; ng++) {
                if (TB) {
                    LDSM_X4(bhf, sBh + boffT + ng * (16 * PITCH_A) + ks * 32);
                    if (TERMS == 3) LDSM_X4(blf, sBl + boffT + ng * (16 * PITCH_A) + ks * 32);
                } else {
                    LDSM_X4_T(bhf, sBh + boffN + ks * (16 * PITCH_BK) + ng * 32);
                    if (TERMS == 3) LDSM_X4_T(blf, sBl + boffN + ks * (16 * PITCH_BK) + ng * 32);
                }
                const int n0 = ng * 2, n1 = ng * 2 + 1;
                #pragma unroll
                for (int mi = 0; mi < 4; mi++) {
                    MMA16816(c[mi][n0], ah[mi], bhf[0], bhf[1]);
                    MMA16816(c[mi][n1], ah[mi], bhf[2], bhf[3]);
                }
                #pragma unroll
                for (int mi = 0; mi < 4; mi++) {
                    MMA16816(c[mi][n0], al[mi], bhf[0], bhf[1]);
                    MMA16816(c[mi][n1], al[mi], bhf[2], bhf[3]);
                }
                if (TERMS == 3) {
                    #pragma unroll
                    for (int mi = 0; mi < 4; mi++) {
                        MMA16816(c[mi][n0], ah[mi], blf[0], blf[1]);
                        MMA16816(c[mi][n1], ah[mi], blf[2], blf[3]);
                    }
                }
            }
        }
    }

    // ---- epilogue (runtime options; uniform branches) ----
    const int rbase = rowBase + wm * 64 + (lane >> 2);
    const int cbase = colBase + wn * 32 + (lane & 3) * 2;
    const float* Resb = Res ? (Res + (size_t)blockIdx.z * sC) : nullptr;
    float* Cb  = C  ? (C  + (size_t)blockIdx.z * sC) : nullptr;
    bf16*  Chb = Ch ? (Ch + (size_t)blockIdx.z * sC) : nullptr;
    bf16*  Clb = Cl ? (Cl + (size_t)blockIdx.z * sC) : nullptr;

    #pragma unroll
    for (int mi = 0; mi < 4; mi++) {
        #pragma unroll
        for (int ni = 0; ni < 4; ni++) {
            const int col = cbase + ni * 8;
            const int r0 = rbase + mi * 16;
            const int r1 = r0 + 8;
            float2 v0 = make_float2(c[mi][ni][0], c[mi][ni][1]);
            float2 v1 = make_float2(c[mi][ni][2], c[mi][ni][3]);
            if (bias) {
                float2 bb = *reinterpret_cast<const float2*>(&bias[col]);
                v0.x += bb.x; v0.y += bb.y; v1.x += bb.x; v1.y += bb.y;
            }
            if (Resb) {
                float2 q0 = *reinterpret_cast<const float2*>(&Resb[(size_t)r0 * N + col]);
                float2 q1 = *reinterpret_cast<const float2*>(&Resb[(size_t)r1 * N + col]);
                v0.x += q0.x; v0.y += q0.y; v1.x += q1.x; v1.y += q1.y;
            }
            if (relu) {
                v0.x = fmaxf(v0.x, 0.f); v0.y = fmaxf(v0.y, 0.f);
                v1.x = fmaxf(v1.x, 0.f); v1.y = fmaxf(v1.y, 0.f);
            }
            if (Cb) {
                *reinterpret_cast<float2*>(&Cb[(size_t)r0 * N + col]) = v0;
                *reinterpret_cast<float2*>(&Cb[(size_t)r1 * N + col]) = v1;
            } else {
                *reinterpret_cast<uint32_t*>(&Chb[(size_t)r0 * N + col]) = pack_hi_lo(v0.x, v0.y, false);
                *reinterpret_cast<uint32_t*>(&Chb[(size_t)r1 * N + col]) = pack_hi_lo(v1.x, v1.y, false);
                *reinterpret_cast<uint32_t*>(&Clb[(size_t)r0 * N + col]) = pack_hi_lo(v0.x, v0.y, true);
                *reinterpret_cast<uint32_t*>(&Clb[(size_t)r1 * N + col]) = pack_hi_lo(v1.x, v1.y, true);
            }
        }
    }
}

// ---------------- softmax: fp32 scores -> bf16 hi/lo probabilities ----------
__global__ void __launch_bounds__(256) softmax_k(
    const float* __restrict__ S, bf16* __restrict__ Ph, bf16* __restrict__ Pl)
{
    const int row = blockIdx.x;
    const float* p = S + (size_t)row * SEQ;
    const int t = threadIdx.x;
    __shared__ float red[256];

    float v[8];
    float m = -1e30f;
    #pragma unroll
    for (int i = 0; i < 8; i++) { v[i] = p[t * 8 + i]; m = fmaxf(m, v[i]); }
    red[t] = m; __syncthreads();
    #pragma unroll
    for (int s = 128; s > 0; s >>= 1) { if (t < s) red[t] = fmaxf(red[t], red[t + s]); __syncthreads(); }
    m = red[0]; __syncthreads();

    float sum = 0.f;
    #pragma unroll
    for (int i = 0; i < 8; i++) { v[i] = expf(v[i] - m); sum += v[i]; }
    red[t] = sum; __syncthreads();
    #pragma unroll
    for (int s = 128; s > 0; s >>= 1) { if (t < s) red[t] += red[t + s]; __syncthreads(); }
    const float inv = 1.f / red[0];

    uint4 h, l;
    #pragma unroll
    for (int i = 0; i < 8; i++) v[i] *= inv;
    h.x = pack_hi_lo(v[0], v[1], false); h.y = pack_hi_lo(v[2], v[3], false);
    h.z = pack_hi_lo(v[4], v[5], false); h.w = pack_hi_lo(v[6], v[7], false);
    l.x = pack_hi_lo(v[0], v[1], true);  l.y = pack_hi_lo(v[2], v[3], true);
    l.z = pack_hi_lo(v[4], v[5], true);  l.w = pack_hi_lo(v[6], v[7], true);
    *reinterpret_cast<uint4*>(&Ph[(size_t)row * SEQ + t * 8]) = h;
    *reinterpret_cast<uint4*>(&Pl[(size_t)row * SEQ + t * 8]) = l;
}

// ---------------- LayerNorm (optionally also emit bf16 hi/lo) ----------------
__global__ void __launch_bounds__(256) layernorm_k(
    const float* __restrict__ in, const float* __restrict__ g,
    const float* __restrict__ b, float* __restrict__ out,
    bf16* __restrict__ oh, bf16* __restrict__ ol)
{
    const int row = blockIdx.x;
    const float* p = in + (size_t)row * EMBED;
    const int t = threadIdx.x;
    __shared__ float r1[256], r2[256];

    float4 v = *reinterpret_cast<const float4*>(&p[t * 4]);
    r1[t] = v.x + v.y + v.z + v.w;
    r2[t] = v.x * v.x + v.y * v.y + v.z * v.z + v.w * v.w;
    __syncthreads();
    #pragma unroll
    for (int st = 128; st > 0; st >>= 1) {
        if (t < st) { r1[t] += r1[t + st]; r2[t] += r2[t + st]; }
        __syncthreads();
    }
    const float mean = r1[0] * (1.f / EMBED);
    const float var  = r2[0] * (1.f / EMBED) - mean * mean;
    const float rstd = rsqrtf(var + 1e-5f);

    float4 gg = *reinterpret_cast<const float4*>(&g[t * 4]);
    float4 bb = *reinterpret_cast<const float4*>(&b[t * 4]);
    float4 o;
    o.x = (v.x - mean) * rstd * gg.x + bb.x;
    o.y = (v.y - mean) * rstd * gg.y + bb.y;
    o.z = (v.z - mean) * rstd * gg.z + bb.z;
    o.w = (v.w - mean) * rstd * gg.w + bb.w;
    *reinterpret_cast<float4*>(&out[(size_t)row * EMBED + t * 4]) = o;
    if (oh) {
        uint2 h, l;
        h.x = pack_hi_lo(o.x, o.y, false); h.y = pack_hi_lo(o.z, o.w, false);
        l.x = pack_hi_lo(o.x, o.y, true);  l.y = pack_hi_lo(o.z, o.w, true);
        *reinterpret_cast<uint2*>(&oh[(size_t)row * EMBED + t * 4]) = h;
        *reinterpret_cast<uint2*>(&ol[(size_t)row * EMBED + t * 4]) = l;
    }
}

// ---------------------------------------------------------------------------
extern "C" void kernel_launch(void* const* d_in, const int* in_sizes, int n_in,
                              void* d_out, int out_size)
{
    const float* src = (const float*)d_in[0];
    const float* bq  = (const float*)d_in[2];
    const float* bk  = (const float*)d_in[4];
    const float* bv  = (const float*)d_in[6];
    const float* bo  = (const float*)d_in[8];
    const float* b1  = (const float*)d_in[10];
    const float* b2  = (const float*)d_in[12];
    const float* g1  = (const float*)d_in[13];
    const float* be1 = (const float*)d_in[14];
    const float* g2  = (const float*)d_in[15];
    const float* be2 = (const float*)d_in[16];

    float *SC, *P1, *X, *P2;
    cudaGetSymbolAddress((void**)&SC, g_SC);
    cudaGetSymbolAddress((void**)&P1, g_P1);
    cudaGetSymbolAddress((void**)&X,  g_X);
    cudaGetSymbolAddress((void**)&P2, g_P2);

    bf16 *srcH,*srcL,*WqH,*WqL,*WkH,*WkL,*WvH,*WvL,*WoH,*WoL,*W1H,*W1L,*W2H,*W2L;
    bf16 *QH,*QL,*KH,*KL,*VH,*VL,*PH,*PL,*AH,*AL,*XH,*XL,*HH,*HL;
    cudaGetSymbolAddress((void**)&srcH, g_srcH); cudaGetSymbolAddress((void**)&srcL, g_srcL);
    cudaGetSymbolAddress((void**)&WqH, g_WqH); cudaGetSymbolAddress((void**)&WqL, g_WqL);
    cudaGetSymbolAddress((void**)&WkH, g_WkH); cudaGetSymbolAddress((void**)&WkL, g_WkL);
    cudaGetSymbolAddress((void**)&WvH, g_WvH); cudaGetSymbolAddress((void**)&WvL, g_WvL);
    cudaGetSymbolAddress((void**)&WoH, g_WoH); cudaGetSymbolAddress((void**)&WoL, g_WoL);
    cudaGetSymbolAddress((void**)&W1H, g_W1H); cudaGetSymbolAddress((void**)&W1L, g_W1L);
    cudaGetSymbolAddress((void**)&W2H, g_W2H); cudaGetSymbolAddress((void**)&W2L, g_W2L);
    cudaGetSymbolAddress((void**)&QH,  g_QH ); cudaGetSymbolAddress((void**)&QL,  g_QL );
    cudaGetSymbolAddress((void**)&KH,  g_KH ); cudaGetSymbolAddress((void**)&KL,  g_KL );
    cudaGetSymbolAddress((void**)&VH,  g_VH ); cudaGetSymbolAddress((void**)&VL,  g_VL );
    cudaGetSymbolAddress((void**)&PH,  g_PH ); cudaGetSymbolAddress((void**)&PL,  g_PL );
    cudaGetSymbolAddress((void**)&AH,  g_AH ); cudaGetSymbolAddress((void**)&AL,  g_AL );
    cudaGetSymbolAddress((void**)&XH,  g_XH ); cudaGetSymbolAddress((void**)&XL,  g_XL );
    cudaGetSymbolAddress((void**)&HH,  g_HH ); cudaGetSymbolAddress((void**)&HL,  g_HL );

    const int SM_NN3 = STAGES * (2 * ATILE + 2 * (64 * PITCH_BK));  // 215040
    const int SM_NT3 = STAGES * (4 * ATILE);                        // 221184
    const int SM_NN2 = STAGES * (2 * ATILE + 1 * (64 * PITCH_BK));  // 162816
    cudaFuncSetAttribute(tgemm<false, 3>, cudaFuncAttributeMaxDynamicSharedMemorySize, SM_NN3);
    cudaFuncSetAttribute(tgemm<true,  3>, cudaFuncAttributeMaxDynamicSharedMemorySize, SM_NT3);
    cudaFuncSetAttribute(tgemm<false, 2>, cudaFuncAttributeMaxDynamicSharedMemorySize, SM_NN2);

    const dim3 blk(256);
    const size_t sQ = (size_t)SEQ * EMBED;
    const size_t sS = (size_t)SEQ * SEQ;

    // ---- one-time splits ----
    split_k<<<(TOK*EMBED/4 + 255)/256, 256>>>(src, srcH, srcL, TOK*EMBED/4);
    split_k<<<(EMBED*EMBED/4 + 255)/256, 256>>>((const float*)d_in[1], WqH, WqL, EMBED*EMBED/4);
    split_k<<<(EMBED*EMBED/4 + 255)/256, 256>>>((const float*)d_in[3], WkH, WkL, EMBED*EMBED/4);
    split_k<<<(EMBED*EMBED/4 + 255)/256, 256>>>((const float*)d_in[5], WvH, WvL, EMBED*EMBED/4);
    split_k<<<(EMBED*EMBED/4 + 255)/256, 256>>>((const float*)d_in[7], WoH, WoL, EMBED*EMBED/4);
    split_k<<<(EMBED*DFF/4 + 255)/256, 256>>>((const float*)d_in[9],  W1H, W1L, EMBED*DFF/4);
    split_k<<<(DFF*EMBED/4 + 255)/256, 256>>>((const float*)d_in[11], W2H, W2L, DFF*EMBED/4);

    // ---- Q/K/V projections (NN + bias, 3-term, bf16-pair out) ----
    tgemm<false, 3><<<dim3(EMBED/128, TOK/128, 1), blk, SM_NN3>>>(
        srcH, srcL, WqH, WqL, bq, nullptr, nullptr, QH, QL, 0, EMBED, EMBED, 0, 0, 0);
    tgemm<false, 3><<<dim3(EMBED/128, TOK/128, 1), blk, SM_NN3>>>(
        srcH, srcL, WkH, WkL, bk, nullptr, nullptr, KH, KL, 0, EMBED, EMBED, 0, 0, 0);
    tgemm<false, 3><<<dim3(EMBED/128, TOK/128, 1), blk, SM_NN3>>>(
        srcH, srcL, WvH, WvL, bv, nullptr, nullptr, VH, VL, 0, EMBED, EMBED, 0, 0, 0);

    // ---- scores = Q @ K^T (NT, batched, 3-term, fp32 out) ----
    tgemm<true, 3><<<dim3(SEQ/128, SEQ/128, BATCH), blk, SM_NT3>>>(
        QH, QL, KH, KL, nullptr, nullptr, SC, nullptr, nullptr, 0, SEQ, EMBED, sQ, sQ, sS);

    softmax_k<<<BATCH * SEQ, 256>>>(SC, PH, PL);

    // ---- attn = P @ V (NN, batched, 2-term: keep P split, drop V-lo) ----
    tgemm<false, 2><<<dim3(EMBED/128, SEQ/128, BATCH), blk, SM_NN2>>>(
        PH, PL, VH, VL, nullptr, nullptr, nullptr, AH, AL, 0, EMBED, SEQ, sS, sQ, sQ);

    // ---- out-proj + bias + residual(src) -> fp32 P1 (2-term: drop Wo-lo) ----
    tgemm<false, 2><<<dim3(EMBED/128, TOK/128, 1), blk, SM_NN2>>>(
        AH, AL, WoH, WoL, bo, src, P1, nullptr, nullptr, 0, EMBED, EMBED, 0, 0, 0);

    layernorm_k<<<TOK, 256>>>(P1, g1, be1, X, XH, XL);

    // ---- FFN up: relu(X @ W1 + b1) -> bf16 pair (2-term) ----
    tgemm<false, 2><<<dim3(DFF/128, TOK/128, 1), blk, SM_NN2>>>(
        XH, XL, W1H, W1L, b1, nullptr, nullptr, HH, HL, 1, DFF, EMBED, 0, 0, 0);

    // ---- FFN down + bias + residual(X) -> fp32 P2 (2-term) ----
    tgemm<false, 2><<<dim3(EMBED/128, TOK/128, 1), blk, SM_NN2>>>(
        HH, HL, W2H, W2L, b2, X, P2, nullptr, nullptr, 0, EMBED, DFF, 0, 0, 0);

    layernorm_k<<<TOK, 256>>>(P2, g2, be2, (float*)d_out, nullptr, nullptr);
}

// round 14
// speedup vs baseline: 3.4250x; 1.1264x over previous
#include <cuda_runtime.h>
#include <cuda_bf16.h>
#include <cstdint>
#include <math.h>

#define EMBED 1024
#define DFF   4096
#define BATCH 4
#define SEQ   2048
#define TOK   (BATCH * SEQ)   // 8192
typedef __nv_bfloat16 bf16;

// ---------------- scratch (static device allocations; allowed) ----------------
__device__ float g_SC[BATCH * SEQ * SEQ];
__device__ float g_P1[TOK * EMBED];
__device__ float g_X [TOK * EMBED];
__device__ float g_P2[TOK * EMBED];
__device__ float g_bqkv[3 * EMBED];
__device__ bf16 g_srcH[TOK * EMBED],  g_srcL[TOK * EMBED];
__device__ bf16 g_WqkvH[3 * EMBED * EMBED], g_WqkvL[3 * EMBED * EMBED];
__device__ bf16 g_WoH[EMBED * EMBED], g_WoL[EMBED * EMBED];
__device__ bf16 g_W1H[EMBED * DFF],   g_W1L[EMBED * DFF];
__device__ bf16 g_W2H[DFF * EMBED],   g_W2L[DFF * EMBED];
__device__ bf16 g_QKVH[3 * TOK * EMBED], g_QKVL[3 * TOK * EMBED];
__device__ bf16 g_PH [BATCH * SEQ * SEQ], g_PL[BATCH * SEQ * SEQ];
__device__ bf16 g_AH [TOK * EMBED],   g_AL [TOK * EMBED];
__device__ bf16 g_XH [TOK * EMBED],   g_XL [TOK * EMBED];
__device__ bf16 g_HH [TOK * DFF],     g_HL [TOK * DFF];

// ---------------- helpers ----------------
__device__ __forceinline__ uint32_t smem_u32(const void* p) {
    uint32_t a;
    asm("{ .reg .u64 t; cvta.to.shared.u64 t, %1; cvt.u32.u64 %0, t; }" : "=r"(a) : "l"(p));
    return a;
}
__device__ __forceinline__ void cp16(uint32_t dst, const void* src) {
    asm volatile("cp.async.cg.shared.global [%0], [%1], 16;" :: "r"(dst), "l"(src));
}
#define CP_COMMIT() asm volatile("cp.async.commit_group;" ::: "memory")
#define CP_WAIT1()  asm volatile("cp.async.wait_group 1;" ::: "memory")
#define CP_WAIT0()  asm volatile("cp.async.wait_group 0;" ::: "memory")

#define LDSM_X4(R, addr)                                                      \
    asm volatile("ldmatrix.sync.aligned.m8n8.x4.shared.b16 {%0,%1,%2,%3}, [%4];" \
                 : "=r"((R)[0]), "=r"((R)[1]), "=r"((R)[2]), "=r"((R)[3])     \
                 : "r"(addr))
#define LDSM_X4_T(R, addr)                                                    \
    asm volatile("ldmatrix.sync.aligned.m8n8.x4.trans.shared.b16 {%0,%1,%2,%3}, [%4];" \
                 : "=r"((R)[0]), "=r"((R)[1]), "=r"((R)[2]), "=r"((R)[3])     \
                 : "r"(addr))
#define MMA16816(D, A, B0, B1)                                                \
    asm volatile("mma.sync.aligned.m16n8k16.row.col.f32.bf16.bf16.f32 "       \
                 "{%0,%1,%2,%3},{%4,%5,%6,%7},{%8,%9},{%0,%1,%2,%3};"         \
                 : "+f"((D)[0]), "+f"((D)[1]), "+f"((D)[2]), "+f"((D)[3])     \
                 : "r"((A)[0]), "r"((A)[1]), "r"((A)[2]), "r"((A)[3]),        \
                   "r"(B0), "r"(B1))

__device__ __forceinline__ uint32_t pack_hi_lo(float a, float b, bool lo) {
    bf16 ha = __float2bfloat16(a), hb = __float2bfloat16(b);
    if (!lo) {
        __nv_bfloat162 t = __halves2bfloat162(ha, hb);
        return *reinterpret_cast<uint32_t*>(&t);
    }
    bf16 la = __float2bfloat16(a - __bfloat162float(ha));
    bf16 lb = __float2bfloat16(b - __bfloat162float(hb));
    __nv_bfloat162 t = __halves2bfloat162(la, lb);
    return *reinterpret_cast<uint32_t*>(&t);
}

// ---------------- split: fp32 -> bf16 hi/lo ----------------
__global__ void __launch_bounds__(256) split_k(
    const float* __restrict__ in, bf16* __restrict__ h, bf16* __restrict__ l, int n4)
{
    int i = blockIdx.x * 256 + threadIdx.x;
    if (i >= n4) return;
    float4 v = reinterpret_cast<const float4*>(in)[i];
    uint2 hh, ll;
    hh.x = pack_hi_lo(v.x, v.y, false); hh.y = pack_hi_lo(v.z, v.w, false);
    ll.x = pack_hi_lo(v.x, v.y, true);  ll.y = pack_hi_lo(v.z, v.w, true);
    reinterpret_cast<uint2*>(h)[i] = hh;
    reinterpret_cast<uint2*>(l)[i] = ll;
}

// ---------------- tensor-core GEMM (cp.async, BK=64, bf16 split) ----------
// C = A @ B (+bias/residual/relu at runtime). Operands pre-split bf16 hi/lo.
// TB=false: B [K,N] (NN).  TB=true: B [N,K] (NT).
// TERMS=3: 3 stages, 1 CTA/SM.  TERMS=2: 2 stages, 2 CTAs/SM (maxregs 128).
// Output: if C != nullptr -> fp32; else bf16 hi/lo pair Ch/Cl.
#define PITCH_A  144
#define PITCH_BK 272
#define ATILE    (128 * PITCH_A)          // 18432

template<bool TB, int TERMS>
__global__ void __launch_bounds__(256, TERMS == 2 ? 2 : 1) tgemm(
    const bf16* __restrict__ Ah, const bf16* __restrict__ Al,
    const bf16* __restrict__ Bh, const bf16* __restrict__ Bl,
    const float* __restrict__ bias, const float* __restrict__ Res,
    float* __restrict__ C, bf16* __restrict__ Ch, bf16* __restrict__ Cl,
    int relu, int N, int K, size_t sA, size_t sB, size_t sC, size_t sBias)
{
    constexpr int BTILE   = TB ? ATILE : (64 * PITCH_BK);    // 18432 / 17408
    constexpr int NB      = (TERMS == 3) ? 2 : 1;
    constexpr int NSTAGES = (TERMS == 3) ? 3 : 2;
    constexpr int STAGE   = 2 * ATILE + NB * BTILE;

    extern __shared__ char smem[];
    const uint32_t sb = smem_u32(smem);

    const int tid  = threadIdx.x;
    const int lane = tid & 31;
    const int wid  = tid >> 5;
    const int wm   = wid >> 2;
    const int wn   = wid & 3;

    const bf16* Abh = Ah + (size_t)blockIdx.z * sA;
    const bf16* Abl = Al + (size_t)blockIdx.z * sA;
    const bf16* Bbh = Bh + (size_t)blockIdx.z * sB;
    const bf16* Bbl = Bl + (size_t)blockIdx.z * sB;
    const int rowBase = blockIdx.y * 128;
    const int colBase = blockIdx.x * 128;

    // ldmatrix lane selectors (validated layout)
    const int rA  = lane & 15;
    const int cA  = (lane >> 4) * 16;
    const int rBt = (lane & 7) | ((lane & 16) >> 1);
    const int cBt = (lane & 8) * 2;
    const int aoff  = (wm * 64 + rA) * PITCH_A + cA;
    const int boffN = rA * PITCH_BK + wn * 64 + cA;
    const int boffT = (wn * 32 + rBt) * PITCH_A + cBt;

    float c[4][4][4];
    #pragma unroll
    for (int i = 0; i < 4; i++)
        #pragma unroll
        for (int j = 0; j < 4; j++)
            #pragma unroll
            for (int q = 0; q < 4; q++) c[i][j][q] = 0.f;

    const int T = K >> 6;   // K-tiles of 64

    auto issue = [&](int t) {
        const int slot = t % NSTAGES;
        const uint32_t base = sb + slot * STAGE;
        const int k0 = t << 6;
        #pragma unroll
        for (int i = 0; i < 4; i++) {
            int idx = tid + i * 256;
            int r = idx >> 3, cc = idx & 7;
            size_t g = (size_t)(rowBase + r) * K + k0 + cc * 8;
            uint32_t s = base + r * PITCH_A + cc * 16;
            cp16(s, Abh + g);
            cp16(s + ATILE, Abl + g);
        }
        if (TB) {
            #pragma unroll
            for (int i = 0; i < 4; i++) {
                int idx = tid + i * 256;
                int r = idx >> 3, cc = idx & 7;
                size_t g = (size_t)(colBase + r) * K + k0 + cc * 8;
                uint32_t s = base + 2 * ATILE + r * PITCH_A + cc * 16;
                cp16(s, Bbh + g);
                if (TERMS == 3) cp16(s + BTILE, Bbl + g);
            }
        } else {
            #pragma unroll
            for (int i = 0; i < 4; i++) {
                int idx = tid + i * 256;
                int r = idx >> 4, cc = idx & 15;
                size_t g = (size_t)(k0 + r) * N + colBase + cc * 8;
                uint32_t s = base + 2 * ATILE + r * PITCH_BK + cc * 16;
                cp16(s, Bbh + g);
                if (TERMS == 3) cp16(s + BTILE, Bbl + g);
            }
        }
    };

    #pragma unroll
    for (int s = 0; s < NSTAGES - 1; s++) { issue(s); CP_COMMIT(); }

    for (int t = 0; t < T; t++) {
        if (TERMS == 3) { CP_WAIT1(); } else { CP_WAIT0(); }
        __syncthreads();
        if (t + NSTAGES - 1 < T) issue(t + NSTAGES - 1);
        CP_COMMIT();

        const uint32_t base = sb + (t % NSTAGES) * STAGE;
        const uint32_t sAh = base;
        const uint32_t sAl = base + ATILE;
        const uint32_t sBh = base + 2 * ATILE;
        const uint32_t sBl = sBh + BTILE;

        uint32_t ah[4][4], al[4][4], bhf[4], blf[4];
        #pragma unroll 1
        for (int ks = 0; ks < 4; ks++) {
            #pragma unroll
            for (int mi = 0; mi < 4; mi++) {
                LDSM_X4(ah[mi], sAh + aoff + mi * (16 * PITCH_A) + ks * 32);
                LDSM_X4(al[mi], sAl + aoff + mi * (16 * PITCH_A) + ks * 32);
            }
            #pragma unroll
            for (int ng = 0; ng < 2; ng++) {
                if (TB) {
                    LDSM_X4(bhf, sBh + boffT + ng * (16 * PITCH_A) + ks * 32);
                    if (TERMS == 3) LDSM_X4(blf, sBl + boffT + ng * (16 * PITCH_A) + ks * 32);
                } else {
                    LDSM_X4_T(bhf, sBh + boffN + ks * (16 * PITCH_BK) + ng * 32);
                    if (TERMS == 3) LDSM_X4_T(blf, sBl + boffN + ks * (16 * PITCH_BK) + ng * 32);
                }
                const int n0 = ng * 2, n1 = ng * 2 + 1;
                #pragma unroll
                for (int mi = 0; mi < 4; mi++) {
                    MMA16816(c[mi][n0], ah[mi], bhf[0], bhf[1]);
                    MMA16816(c[mi][n1], ah[mi], bhf[2], bhf[3]);
                }
                #pragma unroll
                for (int mi = 0; mi < 4; mi++) {
                    MMA16816(c[mi][n0], al[mi], bhf[0], bhf[1]);
                    MMA16816(c[mi][n1], al[mi], bhf[2], bhf[3]);
                }
                if (TERMS == 3) {
                    #pragma unroll
                    for (int mi = 0; mi < 4; mi++) {
                        MMA16816(c[mi][n0], ah[mi], blf[0], blf[1]);
                        MMA16816(c[mi][n1], ah[mi], blf[2], blf[3]);
                    }
                }
            }
        }
    }

    // ---- epilogue (runtime options; uniform branches) ----
    const int rbase = rowBase + wm * 64 + (lane >> 2);
    const int cbase = colBase + wn * 32 + (lane & 3) * 2;
    const float* biasz = bias ? (bias + (size_t)blockIdx.z * sBias) : nullptr;
    const float* Resb = Res ? (Res + (size_t)blockIdx.z * sC) : nullptr;
    float* Cb  = C  ? (C  + (size_t)blockIdx.z * sC) : nullptr;
    bf16*  Chb = Ch ? (Ch + (size_t)blockIdx.z * sC) : nullptr;
    bf16*  Clb = Cl ? (Cl + (size_t)blockIdx.z * sC) : nullptr;

    #pragma unroll
    for (int mi = 0; mi < 4; mi++) {
        #pragma unroll
        for (int ni = 0; ni < 4; ni++) {
            const int col = cbase + ni * 8;
            const int r0 = rbase + mi * 16;
            const int r1 = r0 + 8;
            float2 v0 = make_float2(c[mi][ni][0], c[mi][ni][1]);
            float2 v1 = make_float2(c[mi][ni][2], c[mi][ni][3]);
            if (biasz) {
                float2 bb = *reinterpret_cast<const float2*>(&biasz[col]);
                v0.x += bb.x; v0.y += bb.y; v1.x += bb.x; v1.y += bb.y;
            }
            if (Resb) {
                float2 q0 = *reinterpret_cast<const float2*>(&Resb[(size_t)r0 * N + col]);
                float2 q1 = *reinterpret_cast<const float2*>(&Resb[(size_t)r1 * N + col]);
                v0.x += q0.x; v0.y += q0.y; v1.x += q1.x; v1.y += q1.y;
            }
            if (relu) {
                v0.x = fmaxf(v0.x, 0.f); v0.y = fmaxf(v0.y, 0.f);
                v1.x = fmaxf(v1.x, 0.f); v1.y = fmaxf(v1.y, 0.f);
            }
            if (Cb) {
                *reinterpret_cast<float2*>(&Cb[(size_t)r0 * N + col]) = v0;
                *reinterpret_cast<float2*>(&Cb[(size_t)r1 * N + col]) = v1;
            } else {
                *reinterpret_cast<uint32_t*>(&Chb[(size_t)r0 * N + col]) = pack_hi_lo(v0.x, v0.y, false);
                *reinterpret_cast<uint32_t*>(&Chb[(size_t)r1 * N + col]) = pack_hi_lo(v1.x, v1.y, false);
                *reinterpret_cast<uint32_t*>(&Clb[(size_t)r0 * N + col]) = pack_hi_lo(v0.x, v0.y, true);
                *reinterpret_cast<uint32_t*>(&Clb[(size_t)r1 * N + col]) = pack_hi_lo(v1.x, v1.y, true);
            }
        }
    }
}

// ---------------- softmax: fp32 scores -> bf16 hi/lo probabilities ----------
__global__ void __launch_bounds__(256) softmax_k(
    const float* __restrict__ S, bf16* __restrict__ Ph, bf16* __restrict__ Pl)
{
    const int row = blockIdx.x;
    const float* p = S + (size_t)row * SEQ;
    const int t = threadIdx.x;
    __shared__ float red[256];

    float v[8];
    float m = -1e30f;
    #pragma unroll
    for (int i = 0; i < 8; i++) { v[i] = p[t * 8 + i]; m = fmaxf(m, v[i]); }
    red[t] = m; __syncthreads();
    #pragma unroll
    for (int s = 128; s > 0; s >>= 1) { if (t < s) red[t] = fmaxf(red[t], red[t + s]); __syncthreads(); }
    m = red[0]; __syncthreads();

    float sum = 0.f;
    #pragma unroll
    for (int i = 0; i < 8; i++) { v[i] = expf(v[i] - m); sum += v[i]; }
    red[t] = sum; __syncthreads();
    #pragma unroll
    for (int s = 128; s > 0; s >>= 1) { if (t < s) red[t] += red[t + s]; __syncthreads(); }
    const float inv = 1.f / red[0];

    uint4 h, l;
    #pragma unroll
    for (int i = 0; i < 8; i++) v[i] *= inv;
    h.x = pack_hi_lo(v[0], v[1], false); h.y = pack_hi_lo(v[2], v[3], false);
    h.z = pack_hi_lo(v[4], v[5], false); h.w = pack_hi_lo(v[6], v[7], false);
    l.x = pack_hi_lo(v[0], v[1], true);  l.y = pack_hi_lo(v[2], v[3], true);
    l.z = pack_hi_lo(v[4], v[5], true);  l.w = pack_hi_lo(v[6], v[7], true);
    *reinterpret_cast<uint4*>(&Ph[(size_t)row * SEQ + t * 8]) = h;
    *reinterpret_cast<uint4*>(&Pl[(size_t)row * SEQ + t * 8]) = l;
}

// ---------------- LayerNorm (optionally also emit bf16 hi/lo) ----------------
__global__ void __launch_bounds__(256) layernorm_k(
    const float* __restrict__ in, const float* __restrict__ g,
    const float* __restrict__ b, float* __restrict__ out,
    bf16* __restrict__ oh, bf16* __restrict__ ol)
{
    const int row = blockIdx.x;
    const float* p = in + (size_t)row * EMBED;
    const int t = threadIdx.x;
    __shared__ float r1[256], r2[256];

    float4 v = *reinterpret_cast<const float4*>(&p[t * 4]);
    r1[t] = v.x + v.y + v.z + v.w;
    r2[t] = v.x * v.x + v.y * v.y + v.z * v.z + v.w * v.w;
    __syncthreads();
    #pragma unroll
    for (int st = 128; st > 0; st >>= 1) {
        if (t < st) { r1[t] += r1[t + st]; r2[t] += r2[t + st]; }
        __syncthreads();
    }
    const float mean = r1[0] * (1.f / EMBED);
    const float var  = r2[0] * (1.f / EMBED) - mean * mean;
    const float rstd = rsqrtf(var + 1e-5f);

    float4 gg = *reinterpret_cast<const float4*>(&g[t * 4]);
    float4 bb = *reinterpret_cast<const float4*>(&b[t * 4]);
    float4 o;
    o.x = (v.x - mean) * rstd * gg.x + bb.x;
    o.y = (v.y - mean) * rstd * gg.y + bb.y;
    o.z = (v.z - mean) * rstd * gg.z + bb.z;
    o.w = (v.w - mean) * rstd * gg.w + bb.w;
    *reinterpret_cast<float4*>(&out[(size_t)row * EMBED + t * 4]) = o;
    if (oh) {
        uint2 h, l;
        h.x = pack_hi_lo(o.x, o.y, false); h.y = pack_hi_lo(o.z, o.w, false);
        l.x = pack_hi_lo(o.x, o.y, true);  l.y = pack_hi_lo(o.z, o.w, true);
        *reinterpret_cast<uint2*>(&oh[(size_t)row * EMBED + t * 4]) = h;
        *reinterpret_cast<uint2*>(&ol[(size_t)row * EMBED + t * 4]) = l;
    }
}

// ---------------------------------------------------------------------------
extern "C" void kernel_launch(void* const* d_in, const int* in_sizes, int n_in,
                              void* d_out, int out_size)
{
    const float* src = (const float*)d_in[0];
    const float* bq  = (const float*)d_in[2];
    const float* bk  = (const float*)d_in[4];
    const float* bv  = (const float*)d_in[6];
    const float* bo  = (const float*)d_in[8];
    const float* b1  = (const float*)d_in[10];
    const float* b2  = (const float*)d_in[12];
    const float* g1  = (const float*)d_in[13];
    const float* be1 = (const float*)d_in[14];
    const float* g2  = (const float*)d_in[15];
    const float* be2 = (const float*)d_in[16];

    float *SC, *P1, *X, *P2, *bqkv;
    cudaGetSymbolAddress((void**)&SC, g_SC);
    cudaGetSymbolAddress((void**)&P1, g_P1);
    cudaGetSymbolAddress((void**)&X,  g_X);
    cudaGetSymbolAddress((void**)&P2, g_P2);
    cudaGetSymbolAddress((void**)&bqkv, g_bqkv);

    bf16 *srcH,*srcL,*WqkvH,*WqkvL,*WoH,*WoL,*W1H,*W1L,*W2H,*W2L;
    bf16 *QKVH,*QKVL,*PH,*PL,*AH,*AL,*XH,*XL,*HH,*HL;
    cudaGetSymbolAddress((void**)&srcH, g_srcH); cudaGetSymbolAddress((void**)&srcL, g_srcL);
    cudaGetSymbolAddress((void**)&WqkvH, g_WqkvH); cudaGetSymbolAddress((void**)&WqkvL, g_WqkvL);
    cudaGetSymbolAddress((void**)&WoH, g_WoH); cudaGetSymbolAddress((void**)&WoL, g_WoL);
    cudaGetSymbolAddress((void**)&W1H, g_W1H); cudaGetSymbolAddress((void**)&W1L, g_W1L);
    cudaGetSymbolAddress((void**)&W2H, g_W2H); cudaGetSymbolAddress((void**)&W2L, g_W2L);
    cudaGetSymbolAddress((void**)&QKVH, g_QKVH); cudaGetSymbolAddress((void**)&QKVL, g_QKVL);
    cudaGetSymbolAddress((void**)&PH,  g_PH ); cudaGetSymbolAddress((void**)&PL,  g_PL );
    cudaGetSymbolAddress((void**)&AH,  g_AH ); cudaGetSymbolAddress((void**)&AL,  g_AL );
    cudaGetSymbolAddress((void**)&XH,  g_XH ); cudaGetSymbolAddress((void**)&XL,  g_XL );
    cudaGetSymbolAddress((void**)&HH,  g_HH ); cudaGetSymbolAddress((void**)&HL,  g_HL );

    const int SM_NN3 = 3 * (2 * ATILE + 2 * (64 * PITCH_BK));  // 215040
    const int SM_NT3 = 3 * (4 * ATILE);                        // 221184
    const int SM_NN2 = 2 * (2 * ATILE + 1 * (64 * PITCH_BK));  // 108544
    cudaFuncSetAttribute(tgemm<false, 3>, cudaFuncAttributeMaxDynamicSharedMemorySize, SM_NN3);
    cudaFuncSetAttribute(tgemm<true,  3>, cudaFuncAttributeMaxDynamicSharedMemorySize, SM_NT3);
    cudaFuncSetAttribute(tgemm<false, 2>, cudaFuncAttributeMaxDynamicSharedMemorySize, SM_NN2);

    const dim3 blk(256);
    const size_t sQ = (size_t)SEQ * EMBED;
    const size_t sS = (size_t)SEQ * SEQ;
    const size_t sW = (size_t)EMBED * EMBED;
    const size_t sO = (size_t)TOK * EMBED;

    // ---- one-time splits + bias packing ----
    split_k<<<(TOK*EMBED/4 + 255)/256, 256>>>(src, srcH, srcL, TOK*EMBED/4);
    split_k<<<(EMBED*EMBED/4 + 255)/256, 256>>>((const float*)d_in[1], WqkvH,          WqkvL,          EMBED*EMBED/4);
    split_k<<<(EMBED*EMBED/4 + 255)/256, 256>>>((const float*)d_in[3], WqkvH + sW,     WqkvL + sW,     EMBED*EMBED/4);
    split_k<<<(EMBED*EMBED/4 + 255)/256, 256>>>((const float*)d_in[5], WqkvH + 2*sW,   WqkvL + 2*sW,   EMBED*EMBED/4);
    split_k<<<(EMBED*EMBED/4 + 255)/256, 256>>>((const float*)d_in[7], WoH, WoL, EMBED*EMBED/4);
    split_k<<<(EMBED*DFF/4 + 255)/256, 256>>>((const float*)d_in[9],  W1H, W1L, EMBED*DFF/4);
    split_k<<<(DFF*EMBED/4 + 255)/256, 256>>>((const float*)d_in[11], W2H, W2L, DFF*EMBED/4);
    cudaMemcpyAsync(bqkv,             bq, EMBED*sizeof(float), cudaMemcpyDeviceToDevice);
    cudaMemcpyAsync(bqkv + EMBED,     bk, EMBED*sizeof(float), cudaMemcpyDeviceToDevice);
    cudaMemcpyAsync(bqkv + 2*EMBED,   bv, EMBED*sizeof(float), cudaMemcpyDeviceToDevice);

    // ---- Q/K/V projections: ONE batched launch (z=3, 3-term) ----
    tgemm<false, 3><<<dim3(EMBED/128, TOK/128, 3), blk, SM_NN3>>>(
        srcH, srcL, WqkvH, WqkvL, bqkv, nullptr, nullptr, QKVH, QKVL,
        0, EMBED, EMBED, 0, sW, sO, EMBED);

    bf16 *QH = QKVH,          *QL = QKVL;
    bf16 *KH = QKVH + sO,     *KL = QKVL + sO;
    bf16 *VH = QKVH + 2*sO,   *VL = QKVL + 2*sO;

    // ---- scores = Q @ K^T (NT, batched, 3-term, fp32 out) ----
    tgemm<true, 3><<<dim3(SEQ/128, SEQ/128, BATCH), blk, SM_NT3>>>(
        QH, QL, KH, KL, nullptr, nullptr, SC, nullptr, nullptr, 0, SEQ, EMBED, sQ, sQ, sS, 0);

    softmax_k<<<BATCH * SEQ, 256>>>(SC, PH, PL);

    // ---- attn = P @ V (NN, batched, 2-term) ----
    tgemm<false, 2><<<dim3(EMBED/128, SEQ/128, BATCH), blk, SM_NN2>>>(
        PH, PL, VH, VL, nullptr, nullptr, nullptr, AH, AL, 0, EMBED, SEQ, sS, sQ, sQ, 0);

    // ---- out-proj + bias + residual(src) -> fp32 P1 (2-term) ----
    tgemm<false, 2><<<dim3(EMBED/128, TOK/128, 1), blk, SM_NN2>>>(
        AH, AL, WoH, WoL, bo, src, P1, nullptr, nullptr, 0, EMBED, EMBED, 0, 0, 0, 0);

    layernorm_k<<<TOK, 256>>>(P1, g1, be1, X, XH, XL);

    // ---- FFN up: relu(X @ W1 + b1) -> bf16 pair (2-term) ----
    tgemm<false, 2><<<dim3(DFF/128, TOK/128, 1), blk, SM_NN2>>>(
        XH, XL, W1H, W1L, b1, nullptr, nullptr, HH, HL, 1, DFF, EMBED, 0, 0, 0, 0);

    // ---- FFN down + bias + residual(X) -> fp32 P2 (2-term) ----
    tgemm<false, 2><<<dim3(EMBED/128, TOK/128, 1), blk, SM_NN2>>>(
        HH, HL, W2H, W2L, b2, X, P2, nullptr, nullptr, 0, EMBED, DFF, 0, 0, 0, 0);

    layernorm_k<<<TOK, 256>>>(P2, g2, be2, (float*)d_out, nullptr, nullptr);
}

// round 15
// speedup vs baseline: 3.6072x; 1.0532x over previous
#include <cuda_runtime.h>
#include <cuda_bf16.h>
#include <cstdint>
#include <math.h>

#define EMBED 1024
#define DFF   4096
#define BATCH 4
#define SEQ   2048
#define TOK   (BATCH * SEQ)   // 8192
typedef __nv_bfloat16 bf16;

// ---------------- scratch (static device allocations; allowed) ----------------
__device__ float g_SC[BATCH * SEQ * SEQ];
__device__ float g_P1[TOK * EMBED];
__device__ float g_X [TOK * EMBED];
__device__ float g_P2[TOK * EMBED];
__device__ float g_bqkv[3 * EMBED];
__device__ bf16 g_srcH[TOK * EMBED],  g_srcL[TOK * EMBED];
__device__ bf16 g_WqkvH[3 * EMBED * EMBED], g_WqkvL[3 * EMBED * EMBED];
__device__ bf16 g_WoH[EMBED * EMBED], g_WoL[EMBED * EMBED];
__device__ bf16 g_W1H[EMBED * DFF],   g_W1L[EMBED * DFF];
__device__ bf16 g_W2H[DFF * EMBED],   g_W2L[DFF * EMBED];
__device__ bf16 g_QKVH[3 * TOK * EMBED], g_QKVL[3 * TOK * EMBED];
__device__ bf16 g_PH [BATCH * SEQ * SEQ], g_PL[BATCH * SEQ * SEQ];
__device__ bf16 g_AH [TOK * EMBED],   g_AL [TOK * EMBED];
__device__ bf16 g_XH [TOK * EMBED],   g_XL [TOK * EMBED];
__device__ bf16 g_HH [TOK * DFF],     g_HL [TOK * DFF];

// ---------------- helpers ----------------
__device__ __forceinline__ uint32_t smem_u32(const void* p) {
    uint32_t a;
    asm("{ .reg .u64 t; cvta.to.shared.u64 t, %1; cvt.u32.u64 %0, t; }" : "=r"(a) : "l"(p));
    return a;
}
__device__ __forceinline__ void cp16(uint32_t dst, const void* src) {
    asm volatile("cp.async.cg.shared.global [%0], [%1], 16;" :: "r"(dst), "l"(src));
}
#define CP_COMMIT() asm volatile("cp.async.commit_group;" ::: "memory")
#define CP_WAIT0()  asm volatile("cp.async.wait_group 0;" ::: "memory")

#define LDSM_X4(R, addr)                                                      \
    asm volatile("ldmatrix.sync.aligned.m8n8.x4.shared.b16 {%0,%1,%2,%3}, [%4];" \
                 : "=r"((R)[0]), "=r"((R)[1]), "=r"((R)[2]), "=r"((R)[3])     \
                 : "r"(addr))
#define LDSM_X4_T(R, addr)                                                    \
    asm volatile("ldmatrix.sync.aligned.m8n8.x4.trans.shared.b16 {%0,%1,%2,%3}, [%4];" \
                 : "=r"((R)[0]), "=r"((R)[1]), "=r"((R)[2]), "=r"((R)[3])     \
                 : "r"(addr))
#define MMA16816(D, A, B0, B1)                                                \
    asm volatile("mma.sync.aligned.m16n8k16.row.col.f32.bf16.bf16.f32 "       \
                 "{%0,%1,%2,%3},{%4,%5,%6,%7},{%8,%9},{%0,%1,%2,%3};"         \
                 : "+f"((D)[0]), "+f"((D)[1]), "+f"((D)[2]), "+f"((D)[3])     \
                 : "r"((A)[0]), "r"((A)[1]), "r"((A)[2]), "r"((A)[3]),        \
                   "r"(B0), "r"(B1))

__device__ __forceinline__ uint32_t pack_hi_lo(float a, float b, bool lo) {
    bf16 ha = __float2bfloat16(a), hb = __float2bfloat16(b);
    if (!lo) {
        __nv_bfloat162 t = __halves2bfloat162(ha, hb);
        return *reinterpret_cast<uint32_t*>(&t);
    }
    bf16 la = __float2bfloat16(a - __bfloat162float(ha));
    bf16 lb = __float2bfloat16(b - __bfloat162float(hb));
    __nv_bfloat162 t = __halves2bfloat162(la, lb);
    return *reinterpret_cast<uint32_t*>(&t);
}

// ---------------- split: fp32 -> bf16 hi/lo ----------------
__global__ void __launch_bounds__(256) split_k(
    const float* __restrict__ in, bf16* __restrict__ h, bf16* __restrict__ l, int n4)
{
    int i = blockIdx.x * 256 + threadIdx.x;
    if (i >= n4) return;
    float4 v = reinterpret_cast<const float4*>(in)[i];
    uint2 hh, ll;
    hh.x = pack_hi_lo(v.x, v.y, false); hh.y = pack_hi_lo(v.z, v.w, false);
    ll.x = pack_hi_lo(v.x, v.y, true);  ll.y = pack_hi_lo(v.z, v.w, true);
    reinterpret_cast<uint2*>(h)[i] = hh;
    reinterpret_cast<uint2*>(l)[i] = ll;
}

// ---------------- tensor-core GEMM (cp.async 2-stage, 2 CTA/SM) -----------
// C = A @ B (+bias/residual/relu at runtime). Operands pre-split bf16 hi/lo.
// TB=false: B [K,N] (NN).  TB=true: B [N,K] (NT).
// TERMS=3: BK=32 (pitch 80), loads B-lo.  TERMS=2: BK=64 (pitch 144), no B-lo.
// Both: 2 stages, 2 CTAs/SM. Output: C fp32 if non-null, else bf16 pair Ch/Cl.
#define PITCH_BK 272

template<bool TB, int TERMS>
__global__ void __launch_bounds__(256, 2) tgemm(
    const bf16* __restrict__ Ah, const bf16* __restrict__ Al,
    const bf16* __restrict__ Bh, const bf16* __restrict__ Bl,
    const float* __restrict__ bias, const float* __restrict__ Res,
    float* __restrict__ C, bf16* __restrict__ Ch, bf16* __restrict__ Cl,
    int relu, int N, int K, size_t sA, size_t sB, size_t sC, size_t sBias)
{
    constexpr int BKSZ  = (TERMS == 3) ? 32 : 64;
    constexpr int PA    = (TERMS == 3) ? 80 : 144;   // A/NT-B row pitch (bytes)
    constexpr int AT    = 128 * PA;                  // 10240 / 18432
    constexpr int BTILE = TB ? AT : (BKSZ * PITCH_BK);
    constexpr int NB    = (TERMS == 3) ? 2 : 1;
    constexpr int STAGE = 2 * AT + NB * BTILE;
    constexpr int KS    = BKSZ / 16;                 // 2 / 4
    constexpr int ASH   = (BKSZ == 32) ? 2 : 3;      // A chunk shift (4 / 8 per row)
    constexpr int AIT   = (BKSZ == 32) ? 2 : 4;      // A cp16 iters (x256 thr)
    constexpr int KSH   = (TERMS == 3) ? 5 : 6;      // log2(BKSZ)

    extern __shared__ char smem[];
    const uint32_t sb = smem_u32(smem);

    const int tid  = threadIdx.x;
    const int lane = tid & 31;
    const int wid  = tid >> 5;
    const int wm   = wid >> 2;
    const int wn   = wid & 3;

    const bf16* Abh = Ah + (size_t)blockIdx.z * sA;
    const bf16* Abl = Al + (size_t)blockIdx.z * sA;
    const bf16* Bbh = Bh + (size_t)blockIdx.z * sB;
    const bf16* Bbl = Bl + (size_t)blockIdx.z * sB;
    const int rowBase = blockIdx.y * 128;
    const int colBase = blockIdx.x * 128;

    // ldmatrix lane selectors (both pitches validated in passing rounds)
    const int rA  = lane & 15;
    const int cA  = (lane >> 4) * 16;
    const int rBt = (lane & 7) | ((lane & 16) >> 1);
    const int cBt = (lane & 8) * 2;
    const int aoff  = (wm * 64 + rA) * PA + cA;
    const int boffN = rA * PITCH_BK + wn * 64 + cA;
    const int boffT = (wn * 32 + rBt) * PA + cBt;

    float c[4][4][4];
    #pragma unroll
    for (int i = 0; i < 4; i++)
        #pragma unroll
        for (int j = 0; j < 4; j++)
            #pragma unroll
            for (int q = 0; q < 4; q++) c[i][j][q] = 0.f;

    const int T = K >> KSH;

    auto issue = [&](int t) {
        const uint32_t base = sb + (t & 1) * STAGE;
        const int k0 = t << KSH;
        #pragma unroll
        for (int i = 0; i < AIT; i++) {                 // A hi/lo
            int idx = tid + i * 256;
            int r = idx >> ASH, cc = idx & ((1 << ASH) - 1);
            size_t g = (size_t)(rowBase + r) * K + k0 + cc * 8;
            uint32_t s = base + r * PA + cc * 16;
            cp16(s, Abh + g);
            cp16(s + AT, Abl + g);
        }
        if (TB) {
            #pragma unroll
            for (int i = 0; i < AIT; i++) {
                int idx = tid + i * 256;
                int r = idx >> ASH, cc = idx & ((1 << ASH) - 1);
                size_t g = (size_t)(colBase + r) * K + k0 + cc * 8;
                uint32_t s = base + 2 * AT + r * PA + cc * 16;
                cp16(s, Bbh + g);
                if (TERMS == 3) cp16(s + BTILE, Bbl + g);
            }
        } else {
            #pragma unroll
            for (int i = 0; i < AIT; i++) {             // BKSZ rows x 16 chunks
                int idx = tid + i * 256;
                int r = idx >> 4, cc = idx & 15;
                size_t g = (size_t)(k0 + r) * N + colBase + cc * 8;
                uint32_t s = base + 2 * AT + r * PITCH_BK + cc * 16;
                cp16(s, Bbh + g);
                if (TERMS == 3) cp16(s + BTILE, Bbl + g);
            }
        }
    };

    issue(0); CP_COMMIT();

    for (int t = 0; t < T; t++) {
        CP_WAIT0();
        __syncthreads();
        if (t + 1 < T) issue(t + 1);
        CP_COMMIT();

        const uint32_t base = sb + (t & 1) * STAGE;
        const uint32_t sAh = base;
        const uint32_t sAl = base + AT;
        const uint32_t sBh = base + 2 * AT;
        const uint32_t sBl = sBh + BTILE;

        uint32_t ah[4][4], al[4][4], bhf[4], blf[4];
        #pragma unroll 1
        for (int ks = 0; ks < KS; ks++) {
            #pragma unroll
            for (int mi = 0; mi < 4; mi++) {
                LDSM_X4(ah[mi], sAh + aoff + mi * (16 * PA) + ks * 32);
                LDSM_X4(al[mi], sAl + aoff + mi * (16 * PA) + ks * 32);
            }
            #pragma unroll
            for (int ng = 0; ng < 2; ng++) {
                if (TB) {
                    LDSM_X4(bhf, sBh + boffT + ng * (16 * PA) + ks * 32);
                    if (TERMS == 3) LDSM_X4(blf, sBl + boffT + ng * (16 * PA) + ks * 32);
                } else {
                    LDSM_X4_T(bhf, sBh + boffN + ks * (16 * PITCH_BK) + ng * 32);
                    if (TERMS == 3) LDSM_X4_T(blf, sBl + boffN + ks * (16 * PITCH_BK) + ng * 32);
                }
                const int n0 = ng * 2, n1 = ng * 2 + 1;
                #pragma unroll
                for (int mi = 0; mi < 4; mi++) {
                    MMA16816(c[mi][n0], ah[mi], bhf[0], bhf[1]);
                    MMA16816(c[mi][n1], ah[mi], bhf[2], bhf[3]);
                }
                #pragma unroll
                for (int mi = 0; mi < 4; mi++) {
                    MMA16816(c[mi][n0], al[mi], bhf[0], bhf[1]);
                    MMA16816(c[mi][n1], al[mi], bhf[2], bhf[3]);
                }
                if (TERMS == 3) {
                    #pragma unroll
                    for (int mi = 0; mi < 4; mi++) {
                        MMA16816(c[mi][n0], ah[mi], blf[0], blf[1]);
                        MMA16816(c[mi][n1], ah[mi], blf[2], blf[3]);
                    }
                }
            }
        }
    }

    // ---- epilogue (runtime options; uniform branches) ----
    const int rbase = rowBase + wm * 64 + (lane >> 2);
    const int cbase = colBase + wn * 32 + (lane & 3) * 2;
    const float* biasz = bias ? (bias + (size_t)blockIdx.z * sBias) : nullptr;
    const float* Resb = Res ? (Res + (size_t)blockIdx.z * sC) : nullptr;
    float* Cb  = C  ? (C  + (size_t)blockIdx.z * sC) : nullptr;
    bf16*  Chb = Ch ? (Ch + (size_t)blockIdx.z * sC) : nullptr;
    bf16*  Clb = Cl ? (Cl + (size_t)blockIdx.z * sC) : nullptr;

    #pragma unroll
    for (int mi = 0; mi < 4; mi++) {
        #pragma unroll
        for (int ni = 0; ni < 4; ni++) {
            const int col = cbase + ni * 8;
            const int r0 = rbase + mi * 16;
            const int r1 = r0 + 8;
            float2 v0 = make_float2(c[mi][ni][0], c[mi][ni][1]);
            float2 v1 = make_float2(c[mi][ni][2], c[mi][ni][3]);
            if (biasz) {
                float2 bb = *reinterpret_cast<const float2*>(&biasz[col]);
                v0.x += bb.x; v0.y += bb.y; v1.x += bb.x; v1.y += bb.y;
            }
            if (Resb) {
                float2 q0 = *reinterpret_cast<const float2*>(&Resb[(size_t)r0 * N + col]);
                float2 q1 = *reinterpret_cast<const float2*>(&Resb[(size_t)r1 * N + col]);
                v0.x += q0.x; v0.y += q0.y; v1.x += q1.x; v1.y += q1.y;
            }
            if (relu) {
                v0.x = fmaxf(v0.x, 0.f); v0.y = fmaxf(v0.y, 0.f);
                v1.x = fmaxf(v1.x, 0.f); v1.y = fmaxf(v1.y, 0.f);
            }
            if (Cb) {
                *reinterpret_cast<float2*>(&Cb[(size_t)r0 * N + col]) = v0;
                *reinterpret_cast<float2*>(&Cb[(size_t)r1 * N + col]) = v1;
            } else {
                *reinterpret_cast<uint32_t*>(&Chb[(size_t)r0 * N + col]) = pack_hi_lo(v0.x, v0.y, false);
                *reinterpret_cast<uint32_t*>(&Chb[(size_t)r1 * N + col]) = pack_hi_lo(v1.x, v1.y, false);
                *reinterpret_cast<uint32_t*>(&Clb[(size_t)r0 * N + col]) = pack_hi_lo(v0.x, v0.y, true);
                *reinterpret_cast<uint32_t*>(&Clb[(size_t)r1 * N + col]) = pack_hi_lo(v1.x, v1.y, true);
            }
        }
    }
}

// ---------------- softmax: fp32 scores -> bf16 hi/lo probabilities ----------
__global__ void __launch_bounds__(256) softmax_k(
    const float* __restrict__ S, bf16* __restrict__ Ph, bf16* __restrict__ Pl)
{
    const int row = blockIdx.x;
    const float* p = S + (size_t)row * SEQ;
    const int t = threadIdx.x;
    __shared__ float red[256];

    float v[8];
    float m = -1e30f;
    #pragma unroll
    for (int i = 0; i < 8; i++) { v[i] = p[t * 8 + i]; m = fmaxf(m, v[i]); }
    red[t] = m; __syncthreads();
    #pragma unroll
    for (int s = 128; s > 0; s >>= 1) { if (t < s) red[t] = fmaxf(red[t], red[t + s]); __syncthreads(); }
    m = red[0]; __syncthreads();

    float sum = 0.f;
    #pragma unroll
    for (int i = 0; i < 8; i++) { v[i] = expf(v[i] - m); sum += v[i]; }
    red[t] = sum; __syncthreads();
    #pragma unroll
    for (int s = 128; s > 0; s >>= 1) { if (t < s) red[t] += red[t + s]; __syncthreads(); }
    const float inv = 1.f / red[0];

    uint4 h, l;
    #pragma unroll
    for (int i = 0; i < 8; i++) v[i] *= inv;
    h.x = pack_hi_lo(v[0], v[1], false); h.y = pack_hi_lo(v[2], v[3], false);
    h.z = pack_hi_lo(v[4], v[5], false); h.w = pack_hi_lo(v[6], v[7], false);
    l.x = pack_hi_lo(v[0], v[1], true);  l.y = pack_hi_lo(v[2], v[3], true);
    l.z = pack_hi_lo(v[4], v[5], true);  l.w = pack_hi_lo(v[6], v[7], true);
    *reinterpret_cast<uint4*>(&Ph[(size_t)row * SEQ + t * 8]) = h;
    *reinterpret_cast<uint4*>(&Pl[(size_t)row * SEQ + t * 8]) = l;
}

// ---------------- LayerNorm (optionally also emit bf16 hi/lo) ----------------
__global__ void __launch_bounds__(256) layernorm_k(
    const float* __restrict__ in, const float* __restrict__ g,
    const float* __restrict__ b, float* __restrict__ out,
    bf16* __restrict__ oh, bf16* __restrict__ ol)
{
    const int row = blockIdx.x;
    const float* p = in + (size_t)row * EMBED;
    const int t = threadIdx.x;
    __shared__ float r1[256], r2[256];

    float4 v = *reinterpret_cast<const float4*>(&p[t * 4]);
    r1[t] = v.x + v.y + v.z + v.w;
    r2[t] = v.x * v.x + v.y * v.y + v.z * v.z + v.w * v.w;
    __syncthreads();
    #pragma unroll
    for (int st = 128; st > 0; st >>= 1) {
        if (t < st) { r1[t] += r1[t + st]; r2[t] += r2[t + st]; }
        __syncthreads();
    }
    const float mean = r1[0] * (1.f / EMBED);
    const float var  = r2[0] * (1.f / EMBED) - mean * mean;
    const float rstd = rsqrtf(var + 1e-5f);

    float4 gg = *reinterpret_cast<const float4*>(&g[t * 4]);
    float4 bb = *reinterpret_cast<const float4*>(&b[t * 4]);
    float4 o;
    o.x = (v.x - mean) * rstd * gg.x + bb.x;
    o.y = (v.y - mean) * rstd * gg.y + bb.y;
    o.z = (v.z - mean) * rstd * gg.z + bb.z;
    o.w = (v.w - mean) * rstd * gg.w + bb.w;
    *reinterpret_cast<float4*>(&out[(size_t)row * EMBED + t * 4]) = o;
    if (oh) {
        uint2 h, l;
        h.x = pack_hi_lo(o.x, o.y, false); h.y = pack_hi_lo(o.z, o.w, false);
        l.x = pack_hi_lo(o.x, o.y, true);  l.y = pack_hi_lo(o.z, o.w, true);
        *reinterpret_cast<uint2*>(&oh[(size_t)row * EMBED + t * 4]) = h;
        *reinterpret_cast<uint2*>(&ol[(size_t)row * EMBED + t * 4]) = l;
    }
}

// ---------------------------------------------------------------------------
extern "C" void kernel_launch(void* const* d_in, const int* in_sizes, int n_in,
                              void* d_out, int out_size)
{
    const float* src = (const float*)d_in[0];
    const float* bq  = (const float*)d_in[2];
    const float* bk  = (const float*)d_in[4];
    const float* bv  = (const float*)d_in[6];
    const float* bo  = (const float*)d_in[8];
    const float* b1  = (const float*)d_in[10];
    const float* b2  = (const float*)d_in[12];
    const float* g1  = (const float*)d_in[13];
    const float* be1 = (const float*)d_in[14];
    const float* g2  = (const float*)d_in[15];
    const float* be2 = (const float*)d_in[16];

    float *SC, *P1, *X, *P2, *bqkv;
    cudaGetSymbolAddress((void**)&SC, g_SC);
    cudaGetSymbolAddress((void**)&P1, g_P1);
    cudaGetSymbolAddress((void**)&X,  g_X);
    cudaGetSymbolAddress((void**)&P2, g_P2);
    cudaGetSymbolAddress((void**)&bqkv, g_bqkv);

    bf16 *srcH,*srcL,*WqkvH,*WqkvL,*WoH,*WoL,*W1H,*W1L,*W2H,*W2L;
    bf16 *QKVH,*QKVL,*PH,*PL,*AH,*AL,*XH,*XL,*HH,*HL;
    cudaGetSymbolAddress((void**)&srcH, g_srcH); cudaGetSymbolAddress((void**)&srcL, g_srcL);
    cudaGetSymbolAddress((void**)&WqkvH, g_WqkvH); cudaGetSymbolAddress((void**)&WqkvL, g_WqkvL);
    cudaGetSymbolAddress((void**)&WoH, g_WoH); cudaGetSymbolAddress((void**)&WoL, g_WoL);
    cudaGetSymbolAddress((void**)&W1H, g_W1H); cudaGetSymbolAddress((void**)&W1L, g_W1L);
    cudaGetSymbolAddress((void**)&W2H, g_W2H); cudaGetSymbolAddress((void**)&W2L, g_W2L);
    cudaGetSymbolAddress((void**)&QKVH, g_QKVH); cudaGetSymbolAddress((void**)&QKVL, g_QKVL);
    cudaGetSymbolAddress((void**)&PH,  g_PH ); cudaGetSymbolAddress((void**)&PL,  g_PL );
    cudaGetSymbolAddress((void**)&AH,  g_AH ); cudaGetSymbolAddress((void**)&AL,  g_AL );
    cudaGetSymbolAddress((void**)&XH,  g_XH ); cudaGetSymbolAddress((void**)&XL,  g_XL );
    cudaGetSymbolAddress((void**)&HH,  g_HH ); cudaGetSymbolAddress((void**)&HL,  g_HL );

    // SMEM per CTA (2 stages), x2 CTAs/SM fits 227KB in all cases
    const int SM_NN3 = 2 * (2 * (128*80)  + 2 * (32 * PITCH_BK));  // 75776
    const int SM_NT3 = 2 * (4 * (128*80));                         // 81920
    const int SM_NN2 = 2 * (2 * (128*144) + 1 * (64 * PITCH_BK));  // 108544
    cudaFuncSetAttribute(tgemm<false, 3>, cudaFuncAttributeMaxDynamicSharedMemorySize, SM_NN3);
    cudaFuncSetAttribute(tgemm<true,  3>, cudaFuncAttributeMaxDynamicSharedMemorySize, SM_NT3);
    cudaFuncSetAttribute(tgemm<false, 2>, cudaFuncAttributeMaxDynamicSharedMemorySize, SM_NN2);

    const dim3 blk(256);
    const size_t sQ = (size_t)SEQ * EMBED;
    const size_t sS = (size_t)SEQ * SEQ;
    const size_t sW = (size_t)EMBED * EMBED;
    const size_t sO = (size_t)TOK * EMBED;

    // ---- one-time splits + bias packing ----
    split_k<<<(TOK*EMBED/4 + 255)/256, 256>>>(src, srcH, srcL, TOK*EMBED/4);
    split_k<<<(EMBED*EMBED/4 + 255)/256, 256>>>((const float*)d_in[1], WqkvH,        WqkvL,        EMBED*EMBED/4);
    split_k<<<(EMBED*EMBED/4 + 255)/256, 256>>>((const float*)d_in[3], WqkvH + sW,   WqkvL + sW,   EMBED*EMBED/4);
    split_k<<<(EMBED*EMBED/4 + 255)/256, 256>>>((const float*)d_in[5], WqkvH + 2*sW, WqkvL + 2*sW, EMBED*EMBED/4);
    split_k<<<(EMBED*EMBED/4 + 255)/256, 256>>>((const float*)d_in[7], WoH, WoL, EMBED*EMBED/4);
    split_k<<<(EMBED*DFF/4 + 255)/256, 256>>>((const float*)d_in[9],  W1H, W1L, EMBED*DFF/4);
    split_k<<<(DFF*EMBED/4 + 255)/256, 256>>>((const float*)d_in[11], W2H, W2L, DFF*EMBED/4);
    cudaMemcpyAsync(bqkv,           bq, EMBED*sizeof(float), cudaMemcpyDeviceToDevice);
    cudaMemcpyAsync(bqkv + EMBED,   bk, EMBED*sizeof(float), cudaMemcpyDeviceToDevice);
    cudaMemcpyAsync(bqkv + 2*EMBED, bv, EMBED*sizeof(float), cudaMemcpyDeviceToDevice);

    // ---- Q/K/V projections: ONE batched launch (z=3, 3-term) ----
    tgemm<false, 3><<<dim3(EMBED/128, TOK/128, 3), blk, SM_NN3>>>(
        srcH, srcL, WqkvH, WqkvL, bqkv, nullptr, nullptr, QKVH, QKVL,
        0, EMBED, EMBED, 0, sW, sO, EMBED);

    bf16 *QH = QKVH,        *QL = QKVL;
    bf16 *KH = QKVH + sO,   *KL = QKVL + sO;
    bf16 *VH = QKVH + 2*sO, *VL = QKVL + 2*sO;

    // ---- scores = Q @ K^T (NT, batched, 3-term, fp32 out) ----
    tgemm<true, 3><<<dim3(SEQ/128, SEQ/128, BATCH), blk, SM_NT3>>>(
        QH, QL, KH, KL, nullptr, nullptr, SC, nullptr, nullptr, 0, SEQ, EMBED, sQ, sQ, sS, 0);

    softmax_k<<<BATCH * SEQ, 256>>>(SC, PH, PL);

    // ---- attn = P @ V (NN, batched, 2-term) ----
    tgemm<false, 2><<<dim3(EMBED/128, SEQ/128, BATCH), blk, SM_NN2>>>(
        PH, PL, VH, VL, nullptr, nullptr, nullptr, AH, AL, 0, EMBED, SEQ, sS, sQ, sQ, 0);

    // ---- out-proj + bias + residual(src) -> fp32 P1 (2-term) ----
    tgemm<false, 2><<<dim3(EMBED/128, TOK/128, 1), blk, SM_NN2>>>(
        AH, AL, WoH, WoL, bo, src, P1, nullptr, nullptr, 0, EMBED, EMBED, 0, 0, 0, 0);

    layernorm_k<<<TOK, 256>>>(P1, g1, be1, X, XH, XL);

    // ---- FFN up: relu(X @ W1 + b1) -> bf16 pair (2-term) ----
    tgemm<false, 2><<<dim3(DFF/128, TOK/128, 1), blk, SM_NN2>>>(
        XH, XL, W1H, W1L, b1, nullptr, nullptr, HH, HL, 1, DFF, EMBED, 0, 0, 0, 0);

    // ---- FFN down + bias + residual(X) -> fp32 P2 (2-term) ----
    tgemm<false, 2><<<dim3(EMBED/128, TOK/128, 1), blk, SM_NN2>>>(
        HH, HL, W2H, W2L, b2, X, P2, nullptr, nullptr, 0, EMBED, DFF, 0, 0, 0, 0);

    layernorm_k<<<TOK, 256>>>(P2, g2, be2, (float*)d_out, nullptr, nullptr);
}